// round 14
// baseline (speedup 1.0000x reference)
#include <cuda_runtime.h>
#include <cuda_fp16.h>
#include <math.h>
#include <stdint.h>

#define Bv 4
#define Lv 4096
#define Dv 512
#define Pv 128
#define Vv 8
#define Mv (Bv*Lv)          // 16384
#define NCv 64
#define NC_SH 6
#define NC_MASK 63
#define LCv (Lv/NCv)        // 64
#define PI_F 3.14159265358979323846f
#define INV_SQRT_D 0.044194173824159216f
#define INV_SQRT_P 0.08838834764831845f

// ================= helpers =================
__device__ __forceinline__ uint32_t smem_u32(const void* p) {
    uint32_t a;
    asm("{ .reg .u64 t; cvta.to.shared.u64 t, %1; cvt.u32.u64 %0, t; }" : "=r"(a) : "l"(p));
    return a;
}
__device__ __forceinline__ void cp16(uint32_t s, const void* g) {
    asm volatile("cp.async.cg.shared.global [%0], [%1], 16;" :: "r"(s), "l"(g) : "memory");
}
#define CP_COMMIT() asm volatile("cp.async.commit_group;" ::: "memory")
#define CP_WAIT1()  asm volatile("cp.async.wait_group 1;" ::: "memory")
#define CP_WAIT0()  asm volatile("cp.async.wait_group 0;" ::: "memory")

__device__ __forceinline__ void mma_f16(float* c,
    uint32_t a0, uint32_t a1, uint32_t a2, uint32_t a3,
    uint32_t b0, uint32_t b1)
{
    asm volatile(
        "mma.sync.aligned.m16n8k16.row.col.f32.f16.f16.f32 "
        "{%0,%1,%2,%3}, {%4,%5,%6,%7}, {%8,%9}, {%0,%1,%2,%3};"
        : "+f"(c[0]), "+f"(c[1]), "+f"(c[2]), "+f"(c[3])
        : "r"(a0), "r"(a1), "r"(a2), "r"(a3), "r"(b0), "r"(b1));
}
__device__ __forceinline__ void ldmx4(uint32_t* r, uint32_t addr) {
    asm volatile(
        "ldmatrix.sync.aligned.m8n8.x4.shared.b16 {%0,%1,%2,%3}, [%4];"
        : "=r"(r[0]), "=r"(r[1]), "=r"(r[2]), "=r"(r[3]) : "r"(addr));
}

// ================= scratch =================
__device__ float g_gate[Mv], g_gvraw[(size_t)Mv*8];
__device__ float g_bcat[1792];
__device__ float g_pctx[Bv*NCv*Dv];
__device__ float g_pmc[Bv*NCv*Dv], g_pms[Bv*NCv*Dv], g_pmm[Bv*NCv*Dv];
__device__ float g_pkc[Bv*NCv*Pv*Vv], g_pks[Bv*NCv*Pv*Vv], g_pg[Bv*NCv];
// fp16 tensors
__device__ __half g_wth[3407872];
__device__ __half g_xcath[(size_t)Mv*1024];
__device__ __half g_v1h[(size_t)Mv*512], g_magh[(size_t)Mv*512], g_qdh[(size_t)Mv*512];
__device__ __half g_cqph[(size_t)Mv*128], g_sqph[(size_t)Mv*128];
__device__ __half g_csph[(size_t)Mv*128], g_ssph[(size_t)Mv*128];
__device__ __half g_s1gh[(size_t)Mv*512];
__device__ __half g_posreth[(size_t)Mv*512];
__device__ __half g_ccath[(size_t)Mv*1024];
__device__ __half g_lnh[(size_t)Mv*1024];
__device__ __half g_h1h[(size_t)Mv*1024];

// arena offsets (halves)
#define WT_PROJ 0           // 1792 x 512
#define WT_O    917504
#define WT_S1   1179648
#define WT_S2   1703936
#define WT_T1   1769472
#define WT_T2   2818048

// ================= batched transpose -> fp16 =================
struct TTable {
    const float* src[9];
    __half* dst[9];
    int K[9], N[9], t0[9];
};
__global__ void __launch_bounds__(256) transpose_all(TTable tt) {
    __shared__ float t[32][33];
    int bid = blockIdx.x;
    int w = 8;
#pragma unroll
    for (int i = 8; i >= 0; i--) if (bid >= tt.t0[i]) { w = i; break; }
    int tl = bid - tt.t0[w];
    int K = tt.K[w], N = tt.N[w];
    int tilesK = K >> 5;
    int k0 = (tl % tilesK) * 32, n0 = (tl / tilesK) * 32;
    const float* W = tt.src[w];
    __half* WT = tt.dst[w];
    int tx = threadIdx.x & 31, ty = threadIdx.x >> 5;
#pragma unroll
    for (int i = ty; i < 32; i += 8) t[i][tx] = W[(size_t)(k0 + i) * N + n0 + tx];
    __syncthreads();
#pragma unroll
    for (int i = ty; i < 32; i += 8)
        WT[(size_t)(n0 + i) * K + k0 + tx] = __float2half_rn(t[tx][i]);
}

// pack w_ve (512x8) and w_g (512x1) into proj arena rows 1664..1672
__global__ void pack_veg(const float* __restrict__ w_ve, const float* __restrict__ w_g) {
    int idx = blockIdx.x * blockDim.x + threadIdx.x;
    if (idx < 4096) {
        int k = idx >> 3, v = idx & 7;
        g_wth[WT_PROJ + (size_t)(1664 + v) * 512 + k] = __float2half_rn(w_ve[k * 8 + v]);
    } else if (idx < 4608) {
        int k = idx - 4096;
        g_wth[WT_PROJ + (size_t)1672 * 512 + k] = __float2half_rn(w_g[k]);
    }
}

// ================= bias concat =================
__global__ void bias_concat(const float* b_v, const float* b_m,
                            const float* b_q, const float* b_ke,
                            const float* b_ve, const float* b_g) {
    int i = blockIdx.x * blockDim.x + threadIdx.x;
    if (i < 512)        g_bcat[i] = b_v[i];
    else if (i < 1024)  g_bcat[i] = b_m[i - 512];
    else if (i < 1536)  g_bcat[i] = b_q[i - 1024];
    else if (i < 1664)  g_bcat[i] = b_ke[i - 1536];
    else if (i < 1672)  g_bcat[i] = b_ve[i - 1664];
    else if (i == 1672) g_bcat[i] = b_g[0];
}

// ================= fp16 mma.sync GEMM (128x128 tile, 2-stage, 2 CTAs/SM) =================
// epi: 0 none, 2 exact gelu, 4 +eptr residual (fp32 out),
//      5 sincos(tanh*PI) -> half C, C2,
//      6 merged-proj (v1|mag|qd|ke-sincos|veg). ohalf: C as __half.
#define LDA_H 40
#define STAGE_H (256 * LDA_H)
__global__ void __launch_bounds__(256, 2) mma_gemm(
    const __half* __restrict__ A, const __half* __restrict__ WT,
    const float* __restrict__ bias,
    float* __restrict__ C, float* __restrict__ C2, float* __restrict__ C3,
    float* __restrict__ C4, float* __restrict__ C5,
    int K, int lda, int ldc, int epi, int ohalf, const float* __restrict__ eptr)
{
    extern __shared__ __half smh[];
    const int tid = threadIdx.x, wid = tid >> 5, lane = tid & 31;
    const int warp_m = wid & 3, warp_n = wid >> 2;
    const int n0 = blockIdx.x * 128, m0 = blockIdx.y * 128;
    const int NK = K >> 5;
    const int lq = lane >> 2, lr = lane & 3;

    const int g = lane >> 3, r = lane & 7;
    const uint32_t aoff = ((uint32_t)((warp_m * 32 + (g & 1) * 8 + r) * LDA_H
                           + (g >> 1) * 8)) * 2u;
    const uint32_t boff = ((uint32_t)((warp_n * 64 + (g >> 1) * 8 + r) * LDA_H
                           + (g & 1) * 8)) * 2u;

    const uint32_t sbase = smem_u32(smh);

    float c[2][8][4];
#pragma unroll
    for (int mi = 0; mi < 2; mi++)
#pragma unroll
        for (int j = 0; j < 8; j++)
#pragma unroll
            for (int q = 0; q < 4; q++) c[mi][j][q] = 0.f;

    auto load_tile = [&](int kt, int buf) {
        __half* dst = smh + buf * STAGE_H;
#pragma unroll
        for (int i = 0; i < 2; i++) {
            int idx = tid + i * 256;
            int row = idx >> 2, cq = idx & 3;
            cp16(smem_u32(dst + row * LDA_H + cq * 8),
                 A + (size_t)(m0 + row) * lda + kt * 32 + cq * 8);
        }
#pragma unroll
        for (int i = 0; i < 2; i++) {
            int idx = tid + i * 256;
            int row = idx >> 2, cq = idx & 3;
            cp16(smem_u32(dst + 128 * LDA_H + row * LDA_H + cq * 8),
                 WT + (size_t)(n0 + row) * K + kt * 32 + cq * 8);
        }
        CP_COMMIT();
    };

    load_tile(0, 0);

    for (int kt = 0; kt < NK; kt++) {
        int buf = kt & 1;
        if (kt + 1 < NK) load_tile(kt + 1, buf ^ 1);
        if (kt + 1 < NK) { CP_WAIT1(); } else { CP_WAIT0(); }
        __syncthreads();

        const uint32_t aBase = sbase + (uint32_t)(buf * STAGE_H) * 2u;
        const uint32_t bBase = aBase + 128u * LDA_H * 2u;
#pragma unroll
        for (int ks = 0; ks < 2; ks++) {
            uint32_t kbb = (uint32_t)ks * 32u;
            uint32_t a[2][4];
            ldmx4(a[0], aBase + aoff + kbb);
            ldmx4(a[1], aBase + aoff + 16u * LDA_H * 2u + kbb);
#pragma unroll
            for (int jp = 0; jp < 4; jp++) {
                uint32_t bR[4];
                ldmx4(bR, bBase + boff + (uint32_t)jp * 16u * LDA_H * 2u + kbb);
                int j0 = jp * 2;
                mma_f16(c[0][j0], a[0][0], a[0][1], a[0][2], a[0][3], bR[0], bR[1]);
                mma_f16(c[1][j0], a[1][0], a[1][1], a[1][2], a[1][3], bR[0], bR[1]);
                mma_f16(c[0][j0 + 1], a[0][0], a[0][1], a[0][2], a[0][3], bR[2], bR[3]);
                mma_f16(c[1][j0 + 1], a[1][0], a[1][1], a[1][2], a[1][3], bR[2], bR[3]);
            }
        }
        __syncthreads();
    }

    // ---------------- epilogue ----------------
    float scale1 = (epi == 6) ? fabsf(*eptr) : 0.f;
    int t = n0 >> 7;   // tile index for epi6
#pragma unroll
    for (int mi = 0; mi < 2; mi++) {
#pragma unroll
        for (int j = 0; j < 8; j++) {
            int gm = m0 + warp_m * 32 + mi * 16 + lq;
            int gn = n0 + warp_n * 64 + j * 8 + lr * 2;
            float b0 = bias[gn], b1 = bias[gn + 1];
#pragma unroll
            for (int h = 0; h < 2; h++) {
                int gmr = gm + h * 8;
                float v0 = c[mi][j][h * 2 + 0] + b0;
                float v1 = c[mi][j][h * 2 + 1] + b1;
                if (epi == 6) {
                    if (t < 4) {
                        __half* Ch = (__half*)C;
                        Ch[(size_t)gmr * 512 + gn] = __float2half_rn(v0);
                        Ch[(size_t)gmr * 512 + gn + 1] = __float2half_rn(v1);
                    } else if (t < 8) {
                        __half* Ch = (__half*)C2;
                        size_t oo = (size_t)gmr * 512 + gn - 512;
                        Ch[oo]     = __float2half_rn(scale1 / (1.f + expf(-v0)));
                        Ch[oo + 1] = __float2half_rn(scale1 / (1.f + expf(-v1)));
                    } else if (t < 12) {
                        __half* Ch = (__half*)C3;
                        size_t oo = (size_t)gmr * 512 + gn - 1024;
                        Ch[oo] = __float2half_rn(v0);
                        Ch[oo + 1] = __float2half_rn(v1);
                    } else if (t == 12) {
                        size_t oo = (size_t)gmr * 128 + gn - 1536;
                        float t0 = tanhf(v0) * PI_F, t1 = tanhf(v1) * PI_F;
                        float s0, cc0, s1, cc1;
                        sincosf(t0, &s0, &cc0);
                        sincosf(t1, &s1, &cc1);
                        __half* C4h = (__half*)C4;
                        __half* C5h = (__half*)C5;
                        C4h[oo] = __float2half_rn(cc0); C4h[oo + 1] = __float2half_rn(cc1);
                        C5h[oo] = __float2half_rn(s0);  C5h[oo + 1] = __float2half_rn(s1);
                    } else {
                        int col0 = gn - 1664;
                        if (col0 < 8) g_gvraw[(size_t)gmr * 8 + col0] = v0;
                        else if (col0 == 8) g_gate[gmr] = 1.f / (1.f + expf(-v0));
                        int col1 = col0 + 1;
                        if (col1 < 8) g_gvraw[(size_t)gmr * 8 + col1] = v1;
                        else if (col1 == 8) g_gate[gmr] = 1.f / (1.f + expf(-v1));
                    }
                    continue;
                }
                size_t oo = (size_t)gmr * ldc + gn;
                if (epi == 5) {
                    float t0 = tanhf(v0) * PI_F, t1 = tanhf(v1) * PI_F;
                    float s0, c0, s1, c1;
                    sincosf(t0, &s0, &c0);
                    sincosf(t1, &s1, &c1);
                    ((__half*)C)[oo]      = __float2half_rn(c0);
                    ((__half*)C)[oo + 1]  = __float2half_rn(c1);
                    ((__half*)C2)[oo]     = __float2half_rn(s0);
                    ((__half*)C2)[oo + 1] = __float2half_rn(s1);
                    continue;
                }
                if (epi == 2) {
                    v0 = 0.5f * v0 * (1.f + erff(v0 * 0.70710678118654752f));
                    v1 = 0.5f * v1 * (1.f + erff(v1 * 0.70710678118654752f));
                } else if (epi == 4) {
                    v0 += eptr[oo];
                    v1 += eptr[oo + 1];
                }
                if (ohalf) {
                    __half* Ch = (__half*)C;
                    Ch[oo] = __float2half_rn(v0);
                    Ch[oo + 1] = __float2half_rn(v1);
                } else {
                    C[oo] = v0; C[oo + 1] = v1;
                }
            }
        }
    }
}

// ================= context_avg scan =================
__global__ void ctx_p1(const float* __restrict__ x) {
    int bc = blockIdx.x; int b = bc >> NC_SH, c = bc & NC_MASK;
    int d = blockIdx.y * 128 + threadIdx.x;
    const float* xp = x + ((size_t)(b * Lv + c * LCv)) * Dv + d;
    float s0 = 0.f, s1 = 0.f, s2 = 0.f, s3 = 0.f;
#pragma unroll 4
    for (int i = 0; i < LCv; i += 4) {
        s0 += xp[(size_t)i * Dv];
        s1 += xp[(size_t)(i + 1) * Dv];
        s2 += xp[(size_t)(i + 2) * Dv];
        s3 += xp[(size_t)(i + 3) * Dv];
    }
    g_pctx[(size_t)bc * Dv + d] = (s0 + s1) + (s2 + s3);
}
__global__ void ctx_p2() {
    int idx = blockIdx.x * blockDim.x + threadIdx.x;
    if (idx >= Bv * Dv) return;
    int b = idx / Dv, d = idx % Dv;
    float v[NCv];
#pragma unroll
    for (int c = 0; c < NCv; c++)
        v[c] = g_pctx[((size_t)(b * NCv + c)) * Dv + d];
    float run = 0.f;
#pragma unroll
    for (int c = 0; c < NCv; c++) { float t = v[c]; v[c] = run; run += t; }
#pragma unroll
    for (int c = 0; c < NCv; c++)
        g_pctx[((size_t)(b * NCv + c)) * Dv + d] = v[c];
}
__global__ void ctx_p3(const float* __restrict__ x) {
    int bc = blockIdx.x; int b = bc >> NC_SH, c = bc & NC_MASK;
    int d = blockIdx.y * 128 + threadIdx.x;
    const float* xp = x + ((size_t)(b * Lv + c * LCv)) * Dv + d;
    float s = g_pctx[(size_t)bc * Dv + d];
    for (int i = 0; i < LCv; i++) {
        int l = c * LCv + i;
        float xv = xp[(size_t)i * Dv];
        s += xv;
        size_t row = (size_t)(b * Lv + l);
        g_xcath[row * 1024 + d] = __float2half_rn(xv);
        g_xcath[row * 1024 + 512 + d] = __float2half_rn(s / (float)(l + 1));
    }
}

// ================= mem1 scan + fused pos_ret (half inputs) =================
__global__ void mem1_p1(const float* __restrict__ pos) {
    int bc = blockIdx.x; int b = bc >> NC_SH, c = bc & NC_MASK;
    int d = blockIdx.y * 128 + threadIdx.x;
    size_t base = ((size_t)(b * Lv + c * LCv)) * Dv + d;
    float sc = 0.f, ss = 0.f, sm = 0.f;
    for (int i = 0; i < LCv; i++) {
        int lg = c * LCv + i;
        float mag = __half2float(g_magh[base + (size_t)i * Dv]);
        float v1  = __half2float(g_v1h[base + (size_t)i * Dv]);
        float w = mag * v1;
        float sphi, cphi;
        sincosf(pos[(size_t)lg * Dv + d], &sphi, &cphi);
        sc += w * cphi;
        ss += w * sphi;
        sm += mag;
    }
    size_t o = (size_t)bc * Dv + d;
    g_pmc[o] = sc; g_pms[o] = ss; g_pmm[o] = sm;
}
__global__ void mem1_p2() {
    int idx = blockIdx.x * blockDim.x + threadIdx.x;
    if (idx >= Bv * Dv) return;
    int sel = blockIdx.y;
    float* arr = (sel == 0) ? g_pmc : ((sel == 1) ? g_pms : g_pmm);
    int b = idx / Dv, d = idx % Dv;
    float v[NCv];
#pragma unroll
    for (int c = 0; c < NCv; c++)
        v[c] = arr[((size_t)(b * NCv + c)) * Dv + d];
    float run = 0.f;
#pragma unroll
    for (int c = 0; c < NCv; c++) { float t = v[c]; v[c] = run; run += t; }
#pragma unroll
    for (int c = 0; c < NCv; c++)
        arr[((size_t)(b * NCv + c)) * Dv + d] = v[c];
}
__global__ void mem1_p3(const float* __restrict__ pos) {
    int bc = blockIdx.x; int b = bc >> NC_SH, c = bc & NC_MASK;
    int d = blockIdx.y * 128 + threadIdx.x;
    size_t base = ((size_t)(b * Lv + c * LCv)) * Dv + d;
    size_t po = (size_t)bc * Dv + d;
    float sc = g_pmc[po], ss = g_pms[po], sm = g_pmm[po];
    for (int i = 0; i < LCv; i++) {
        int lg = c * LCv + i;
        float mag = __half2float(g_magh[base + (size_t)i * Dv]);
        float v1  = __half2float(g_v1h[base + (size_t)i * Dv]);
        float w = mag * v1;
        float pp = pos[(size_t)lg * Dv + d];
        float sphi, cphi;
        sincosf(pp, &sphi, &cphi);
        sc += w * cphi;
        ss += w * sphi;
        sm += mag;
        float ph = pp + __half2float(g_qdh[base + (size_t)i * Dv]);
        float sq, cq;
        sincosf(ph, &sq, &cq);
        g_posreth[base + (size_t)i * Dv] = __float2half_rn(
            (sc * cq + ss * sq) * rsqrtf(sm + 1e-8f) * INV_SQRT_D);
    }
}

// ================= kv phasor scan: 8-token chunked, warp-per-v =================
__global__ void __launch_bounds__(256) kv_p1() {
    __shared__ float s_csp[8][128], s_ssp[8][128];
    __shared__ float s_gv[8][8], s_gate[8];
    int bc = blockIdx.x; int b = bc >> NC_SH, c = bc & NC_MASK;
    int tid = threadIdx.x, w = tid >> 5, l = tid & 31;
    int mbase = b * Lv + c * LCv;
    float aC[4] = {0, 0, 0, 0}, aS[4] = {0, 0, 0, 0};
    float gs = 0.f;
    for (int r0 = 0; r0 < LCv; r0 += 8) {
#pragma unroll
        for (int e = tid; e < 1024; e += 256) {
            int i = e >> 7, p = e & 127;
            size_t mm = (size_t)(mbase + r0 + i) * 128 + p;
            s_csp[i][p] = __half2float(g_csph[mm]);
            s_ssp[i][p] = __half2float(g_ssph[mm]);
        }
        if (tid < 64) s_gv[tid >> 3][tid & 7] = g_gvraw[(size_t)(mbase + r0 + (tid >> 3)) * 8 + (tid & 7)];
        if (tid < 8) s_gate[tid] = g_gate[mbase + r0 + tid];
        __syncthreads();
#pragma unroll
        for (int i = 0; i < 8; i++) {
            float gvv = s_gv[i][w] * s_gate[i];
            float4 cv = ((const float4*)s_csp[i])[l];
            float4 sv = ((const float4*)s_ssp[i])[l];
            aC[0] += cv.x * gvv; aC[1] += cv.y * gvv;
            aC[2] += cv.z * gvv; aC[3] += cv.w * gvv;
            aS[0] += sv.x * gvv; aS[1] += sv.y * gvv;
            aS[2] += sv.z * gvv; aS[3] += sv.w * gvv;
            gs += s_gate[i];
        }
        __syncthreads();
    }
#pragma unroll
    for (int j = 0; j < 4; j++) {
        size_t o = (size_t)bc * 1024 + (size_t)(4 * l + j) * 8 + w;
        g_pkc[o] = aC[j]; g_pks[o] = aS[j];
    }
    if (tid == 0) g_pg[bc] = gs;
}
__global__ void kv_p2() {
    int idx = blockIdx.x * blockDim.x + threadIdx.x;
    if (idx < Bv * Pv * Vv) {
        float* arr = blockIdx.y ? g_pks : g_pkc;
        int b = idx >> 10, pv = idx & 1023;
        float v[NCv];
#pragma unroll
        for (int c = 0; c < NCv; c++)
            v[c] = arr[((size_t)(b * NCv + c)) * 1024 + pv];
        float run = 0.f;
#pragma unroll
        for (int c = 0; c < NCv; c++) { float t = v[c]; v[c] = run; run += t; }
#pragma unroll
        for (int c = 0; c < NCv; c++)
            arr[((size_t)(b * NCv + c)) * 1024 + pv] = v[c];
    }
    if (blockIdx.x == 0 && blockIdx.y == 0 && idx < Bv) {
        float v[NCv];
#pragma unroll
        for (int c = 0; c < NCv; c++) v[c] = g_pg[(size_t)idx * NCv + c];
        float run = 0.f;
#pragma unroll
        for (int c = 0; c < NCv; c++) { float t = v[c]; v[c] = run; run += t; }
#pragma unroll
        for (int c = 0; c < NCv; c++) g_pg[(size_t)idx * NCv + c] = v[c];
    }
}
__global__ void __launch_bounds__(256) kv_p3(
    const float* __restrict__ w_kv, const float* __restrict__ b_kv)
{
    __shared__ float s_csp[8][128], s_ssp[8][128], s_cqp[8][128], s_sqp[8][128];
    __shared__ float s_gv[8][8], s_gate[8], s_kvr[8][8];
    __shared__ float s_wkv[8 * 512];
    __shared__ float s_bkv[512];
    int bc = blockIdx.x; int b = bc >> NC_SH, c = bc & NC_MASK;
    int tid = threadIdx.x, w = tid >> 5, l = tid & 31;
    int mbase = b * Lv + c * LCv;
    for (int i = tid; i < 8 * 512; i += 256) s_wkv[i] = w_kv[i];
    for (int i = tid; i < 512; i += 256) s_bkv[i] = b_kv[i];
    float aC[4], aS[4];
#pragma unroll
    for (int j = 0; j < 4; j++) {
        size_t o = (size_t)bc * 1024 + (size_t)(4 * l + j) * 8 + w;
        aC[j] = g_pkc[o]; aS[j] = g_pks[o];
    }
    float gsum = g_pg[bc];
    for (int r0 = 0; r0 < LCv; r0 += 8) {
#pragma unroll
        for (int e = tid; e < 1024; e += 256) {
            int i = e >> 7, p = e & 127;
            size_t mm = (size_t)(mbase + r0 + i) * 128 + p;
            s_csp[i][p] = __half2float(g_csph[mm]);
            s_ssp[i][p] = __half2float(g_ssph[mm]);
            s_cqp[i][p] = __half2float(g_cqph[mm]);
            s_sqp[i][p] = __half2float(g_sqph[mm]);
        }
        if (tid < 64) s_gv[tid >> 3][tid & 7] = g_gvraw[(size_t)(mbase + r0 + (tid >> 3)) * 8 + (tid & 7)];
        if (tid < 8) s_gate[tid] = g_gate[mbase + r0 + tid];
        __syncthreads();
#pragma unroll
        for (int i = 0; i < 8; i++) {
            float gvv = s_gv[i][w] * s_gate[i];
            float4 cv = ((const float4*)s_csp[i])[l];
            float4 sv = ((const float4*)s_ssp[i])[l];
            float4 cq = ((const float4*)s_cqp[i])[l];
            float4 sq = ((const float4*)s_sqp[i])[l];
            aC[0] += cv.x * gvv; aS[0] += sv.x * gvv;
            aC[1] += cv.y * gvv; aS[1] += sv.y * gvv;
            aC[2] += cv.z * gvv; aS[2] += sv.z * gvv;
            aC[3] += cv.w * gvv; aS[3] += sv.w * gvv;
            float pr = cq.x * aC[0] + sq.x * aS[0]
                     + cq.y * aC[1] + sq.y * aS[1]
                     + cq.z * aC[2] + sq.z * aS[2]
                     + cq.w * aC[3] + sq.w * aS[3];
#pragma unroll
            for (int o = 16; o; o >>= 1)
                pr += __shfl_xor_sync(0xffffffffu, pr, o);
            gsum += s_gate[i];
            if (l == 0)
                s_kvr[i][w] = pr * rsqrtf(fmaxf(gsum, 1.0f)) * INV_SQRT_P;
        }
        __syncthreads();
#pragma unroll
        for (int k = 0; k < 16; k++) {
            int idx = tid + k * 256;
            int tok = idx >> 9, n = idx & 511;
            float o = s_bkv[n];
#pragma unroll
            for (int v = 0; v < 8; v++)
                o += s_kvr[tok][v] * s_wkv[v * 512 + n];
            g_ccath[(size_t)(mbase + r0 + tok) * 1024 + 512 + n] = __float2half_rn(o);
        }
        __syncthreads();
    }
}

// ================= LayerNorm (half in/out) =================
__global__ void __launch_bounds__(256) ln_kernel(
    const float* __restrict__ lng, const float* __restrict__ lnb)
{
    int m = blockIdx.x, tid = threadIdx.x;
    const __half2* row = (const __half2*)(g_ccath + (size_t)m * 1024);
    __half2 h0 = row[tid * 2], h1 = row[tid * 2 + 1];
    float2 f0 = __half22float2(h0), f1 = __half22float2(h1);
    float s = f0.x + f0.y + f1.x + f1.y;
    float q = f0.x * f0.x + f0.y * f0.y + f1.x * f1.x + f1.y * f1.y;
#pragma unroll
    for (int o = 16; o; o >>= 1) {
        s += __shfl_xor_sync(0xffffffffu, s, o);
        q += __shfl_xor_sync(0xffffffffu, q, o);
    }
    __shared__ float ss[8], sq[8];
    __shared__ float smu, srs;
    if ((tid & 31) == 0) { ss[tid >> 5] = s; sq[tid >> 5] = q; }
    __syncthreads();
    if (tid == 0) {
        float S = 0.f, Q = 0.f;
#pragma unroll
        for (int w = 0; w < 8; w++) { S += ss[w]; Q += sq[w]; }
        float mu = S * (1.f / 1024.f);
        float var = Q * (1.f / 1024.f) - mu * mu;
        smu = mu; srs = rsqrtf(var + 1e-5f);
    }
    __syncthreads();
    float mu = smu, rs = srs;
    float4 g4 = ((const float4*)lng)[tid];
    float4 b4 = ((const float4*)lnb)[tid];
    __half2* oh = (__half2*)(g_lnh + (size_t)m * 1024);
    oh[tid * 2]     = __floats2half2_rn((f0.x - mu) * rs * g4.x + b4.x,
                                        (f0.y - mu) * rs * g4.y + b4.y);
    oh[tid * 2 + 1] = __floats2half2_rn((f1.x - mu) * rs * g4.z + b4.z,
                                        (f1.y - mu) * rs * g4.w + b4.w);
}

// ================= launch =================
extern "C" void kernel_launch(void* const* d_in, const int* in_sizes, int n_in,
                              void* d_out, int out_size)
{
    const float* x    = (const float*)d_in[0];
    const float* pos  = (const float*)d_in[1];
    const float* ms   = (const float*)d_in[2];
    const float* w_v  = (const float*)d_in[3];
    const float* b_v  = (const float*)d_in[4];
    const float* w_o  = (const float*)d_in[5];
    const float* b_o  = (const float*)d_in[6];
    const float* w_m  = (const float*)d_in[7];
    const float* b_m  = (const float*)d_in[8];
    const float* w_q  = (const float*)d_in[9];
    const float* b_q  = (const float*)d_in[10];
    const float* w_ke = (const float*)d_in[11];
    const float* b_ke = (const float*)d_in[12];
    const float* w_ve = (const float*)d_in[13];
    const float* b_ve = (const float*)d_in[14];
    const float* w_s1 = (const float*)d_in[15];
    const float* b_s1 = (const float*)d_in[16];
    const float* w_s2 = (const float*)d_in[17];
    const float* b_s2 = (const float*)d_in[18];
    const float* w_g  = (const float*)d_in[19];
    const float* b_g  = (const float*)d_in[20];
    const float* w_kv = (const float*)d_in[21];
    const float* b_kv = (const float*)d_in[22];
    const float* lng  = (const float*)d_in[23];
    const float* lnb  = (const float*)d_in[24];
    const float* w_t1 = (const float*)d_in[25];
    const float* b_t1 = (const float*)d_in[26];
    const float* w_t2 = (const float*)d_in[27];
    const float* b_t2 = (const float*)d_in[28];
    float* out = (float*)d_out;

    float *p_bcat;
    __half *p_wth, *p_xcath, *p_v1h, *p_magh, *p_qdh, *p_cqph, *p_sqph,
           *p_csph, *p_ssph, *p_s1gh, *p_posreth, *p_ccath, *p_lnh, *p_h1h;
    cudaGetSymbolAddress((void**)&p_bcat, g_bcat);
    cudaGetSymbolAddress((void**)&p_wth, g_wth);
    cudaGetSymbolAddress((void**)&p_xcath, g_xcath);
    cudaGetSymbolAddress((void**)&p_v1h, g_v1h);
    cudaGetSymbolAddress((void**)&p_magh, g_magh);
    cudaGetSymbolAddress((void**)&p_qdh, g_qdh);
    cudaGetSymbolAddress((void**)&p_cqph, g_cqph);
    cudaGetSymbolAddress((void**)&p_sqph, g_sqph);
    cudaGetSymbolAddress((void**)&p_csph, g_csph);
    cudaGetSymbolAddress((void**)&p_ssph, g_ssph);
    cudaGetSymbolAddress((void**)&p_s1gh, g_s1gh);
    cudaGetSymbolAddress((void**)&p_posreth, g_posreth);
    cudaGetSymbolAddress((void**)&p_ccath, g_ccath);
    cudaGetSymbolAddress((void**)&p_lnh, g_lnh);
    cudaGetSymbolAddress((void**)&p_h1h, g_h1h);

    __half* wt_proj = p_wth + WT_PROJ;
    __half* wt_o    = p_wth + WT_O;
    __half* wt_s1   = p_wth + WT_S1;
    __half* wt_s2   = p_wth + WT_S2;
    __half* wt_t1   = p_wth + WT_T1;
    __half* wt_t2   = p_wth + WT_T2;

    const int SMEM = 2 * STAGE_H * 2;  // 40960 B
    cudaFuncSetAttribute(mma_gemm, cudaFuncAttributeMaxDynamicSharedMemorySize, SMEM);

    TTable tt;
    tt.src[0] = w_v;  tt.dst[0] = wt_proj;              tt.K[0] = 512;  tt.N[0] = 512;
    tt.src[1] = w_m;  tt.dst[1] = wt_proj + 512 * 512;  tt.K[1] = 512;  tt.N[1] = 512;
    tt.src[2] = w_q;  tt.dst[2] = wt_proj + 1024 * 512; tt.K[2] = 512;  tt.N[2] = 512;
    tt.src[3] = w_ke; tt.dst[3] = wt_proj + 1536 * 512; tt.K[3] = 512;  tt.N[3] = 128;
    tt.src[4] = w_o;  tt.dst[4] = wt_o;                 tt.K[4] = 512;  tt.N[4] = 512;
    tt.src[5] = w_s1; tt.dst[5] = wt_s1;                tt.K[5] = 1024; tt.N[5] = 512;
    tt.src[6] = w_s2; tt.dst[6] = wt_s2;                tt.K[6] = 512;  tt.N[6] = 128;
    tt.src[7] = w_t1; tt.dst[7] = wt_t1;                tt.K[7] = 1024; tt.N[7] = 1024;
    tt.src[8] = w_t2; tt.dst[8] = wt_t2;                tt.K[8] = 1024; tt.N[8] = 512;
    int acc = 0;
    for (int i = 0; i < 9; i++) {
        tt.t0[i] = acc;
        acc += (tt.K[i] >> 5) * (tt.N[i] >> 5);
    }
    transpose_all<<<acc, 256>>>(tt);
    pack_veg<<<18, 256>>>(w_ve, w_g);
    bias_concat<<<7, 256>>>(b_v, b_m, b_q, b_ke, b_ve, b_g);

    dim3 tb(256);
    dim3 gScan(Bv * NCv, Dv / 128);

    ctx_p1<<<gScan, 128>>>(x);
    ctx_p2<<<(Bv * Dv + 255) / 256, 256>>>();
    ctx_p3<<<gScan, 128>>>(x);

    // merged projections: v | mag | qd | ke-sincos | ve+gate
    mma_gemm<<<dim3(14, 128), tb, SMEM>>>(p_xcath, wt_proj, p_bcat,
        (float*)p_v1h, (float*)p_magh, (float*)p_qdh,
        (float*)p_cqph, (float*)p_sqph, 512, 1024, 512, 6, 0, ms);
    mma_gemm<<<dim3(4, 128), tb, SMEM>>>(p_xcath, wt_s1, b_s1,
        (float*)p_s1gh, nullptr, nullptr, nullptr, nullptr, 1024, 1024, 512, 2, 1, nullptr);
    mma_gemm<<<dim3(1, 128), tb, SMEM>>>(p_s1gh, wt_s2, b_s2,
        (float*)p_csph, (float*)p_ssph, nullptr, nullptr, nullptr, 512, 512, 128, 5, 0, nullptr);

    // mem1 scan + pos_out
    mem1_p1<<<gScan, 128>>>(pos);
    mem1_p2<<<dim3((Bv * Dv + 255) / 256, 3), 256>>>();
    mem1_p3<<<gScan, 128>>>(pos);
    mma_gemm<<<dim3(4, 128), tb, SMEM>>>(p_posreth, wt_o, b_o,
        (float*)p_ccath, nullptr, nullptr, nullptr, nullptr, 512, 512, 1024, 0, 1, nullptr);

    // kv scan + retrieval + fused kv_out
    kv_p1<<<Bv * NCv, 256>>>();
    kv_p2<<<dim3((Bv * Pv * Vv + 255) / 256, 2), 256>>>();
    kv_p3<<<Bv * NCv, 256>>>(w_kv, b_kv);

    // LN + output MLP + residual
    ln_kernel<<<Mv, 256>>>(lng, lnb);
    mma_gemm<<<dim3(8, 128), tb, SMEM>>>(p_lnh, wt_t1, b_t1,
        (float*)p_h1h, nullptr, nullptr, nullptr, nullptr, 1024, 1024, 1024, 2, 1, nullptr);
    mma_gemm<<<dim3(4, 128), tb, SMEM>>>(p_h1h, wt_t2, b_t2,
        out, nullptr, nullptr, nullptr, nullptr, 1024, 1024, 512, 4, 0, x);
}

// round 15
// speedup vs baseline: 1.0507x; 1.0507x over previous
#include <cuda_runtime.h>
#include <cuda_fp16.h>
#include <math.h>
#include <stdint.h>

#define Bv 4
#define Lv 4096
#define Dv 512
#define Pv 128
#define Vv 8
#define Mv (Bv*Lv)          // 16384
#define NCv 64
#define NC_SH 6
#define NC_MASK 63
#define LCv (Lv/NCv)        // 64
#define PI_F 3.14159265358979323846f
#define INV_SQRT_D 0.044194173824159216f
#define INV_SQRT_P 0.08838834764831845f

// ================= helpers =================
__device__ __forceinline__ uint32_t smem_u32(const void* p) {
    uint32_t a;
    asm("{ .reg .u64 t; cvta.to.shared.u64 t, %1; cvt.u32.u64 %0, t; }" : "=r"(a) : "l"(p));
    return a;
}
__device__ __forceinline__ void cp16(uint32_t s, const void* g) {
    asm volatile("cp.async.cg.shared.global [%0], [%1], 16;" :: "r"(s), "l"(g) : "memory");
}
#define CP_COMMIT() asm volatile("cp.async.commit_group;" ::: "memory")
#define CP_WAIT1()  asm volatile("cp.async.wait_group 1;" ::: "memory")
#define CP_WAIT0()  asm volatile("cp.async.wait_group 0;" ::: "memory")

__device__ __forceinline__ void mma_f16(float* c,
    uint32_t a0, uint32_t a1, uint32_t a2, uint32_t a3,
    uint32_t b0, uint32_t b1)
{
    asm volatile(
        "mma.sync.aligned.m16n8k16.row.col.f32.f16.f16.f32 "
        "{%0,%1,%2,%3}, {%4,%5,%6,%7}, {%8,%9}, {%0,%1,%2,%3};"
        : "+f"(c[0]), "+f"(c[1]), "+f"(c[2]), "+f"(c[3])
        : "r"(a0), "r"(a1), "r"(a2), "r"(a3), "r"(b0), "r"(b1));
}
__device__ __forceinline__ void ldmx4(uint32_t* r, uint32_t addr) {
    asm volatile(
        "ldmatrix.sync.aligned.m8n8.x4.shared.b16 {%0,%1,%2,%3}, [%4];"
        : "=r"(r[0]), "=r"(r[1]), "=r"(r[2]), "=r"(r[3]) : "r"(addr));
}

// ================= scratch =================
__device__ float g_gate[Mv], g_gvraw[(size_t)Mv*8];
__device__ float g_bcat[1792];
__device__ float g_pctx[Bv*NCv*Dv];
__device__ float g_pmc[Bv*NCv*Dv], g_pms[Bv*NCv*Dv], g_pmm[Bv*NCv*Dv];
__device__ float g_pkc[Bv*NCv*Pv*Vv], g_pks[Bv*NCv*Pv*Vv], g_pg[Bv*NCv];
// fp16 tensors
__device__ __half g_wth[3407872];
__device__ __half g_xcath[(size_t)Mv*1024];
__device__ __half g_v1h[(size_t)Mv*512], g_magh[(size_t)Mv*512], g_qdh[(size_t)Mv*512];
__device__ __half g_cqph[(size_t)Mv*128], g_sqph[(size_t)Mv*128];
__device__ __half g_csph[(size_t)Mv*128], g_ssph[(size_t)Mv*128];
__device__ __half g_s1gh[(size_t)Mv*512];
__device__ __half g_posreth[(size_t)Mv*512];
__device__ __half g_ccath[(size_t)Mv*1024];
__device__ __half g_lnh[(size_t)Mv*1024];
__device__ __half g_h1h[(size_t)Mv*1024];

// arena offsets (halves)
#define WT_PROJ 0           // 1792 x 512
#define WT_O    917504
#define WT_S1   1179648
#define WT_S2   1703936
#define WT_T1   1769472
#define WT_T2   2818048

// ================= batched transpose -> fp16 =================
struct TTable {
    const float* src[9];
    __half* dst[9];
    int K[9], N[9], t0[9];
};
__global__ void __launch_bounds__(256) transpose_all(TTable tt) {
    __shared__ float t[32][33];
    int bid = blockIdx.x;
    int w = 8;
#pragma unroll
    for (int i = 8; i >= 0; i--) if (bid >= tt.t0[i]) { w = i; break; }
    int tl = bid - tt.t0[w];
    int K = tt.K[w], N = tt.N[w];
    int tilesK = K >> 5;
    int k0 = (tl % tilesK) * 32, n0 = (tl / tilesK) * 32;
    const float* W = tt.src[w];
    __half* WT = tt.dst[w];
    int tx = threadIdx.x & 31, ty = threadIdx.x >> 5;
#pragma unroll
    for (int i = ty; i < 32; i += 8) t[i][tx] = W[(size_t)(k0 + i) * N + n0 + tx];
    __syncthreads();
#pragma unroll
    for (int i = ty; i < 32; i += 8)
        WT[(size_t)(n0 + i) * K + k0 + tx] = __float2half_rn(t[tx][i]);
}

// pack w_ve (512x8) and w_g (512x1) into proj arena rows 1664..1672
__global__ void pack_veg(const float* __restrict__ w_ve, const float* __restrict__ w_g) {
    int idx = blockIdx.x * blockDim.x + threadIdx.x;
    if (idx < 4096) {
        int k = idx >> 3, v = idx & 7;
        g_wth[WT_PROJ + (size_t)(1664 + v) * 512 + k] = __float2half_rn(w_ve[k * 8 + v]);
    } else if (idx < 4608) {
        int k = idx - 4096;
        g_wth[WT_PROJ + (size_t)1672 * 512 + k] = __float2half_rn(w_g[k]);
    }
}

// ================= bias concat =================
__global__ void bias_concat(const float* b_v, const float* b_m,
                            const float* b_q, const float* b_ke,
                            const float* b_ve, const float* b_g) {
    int i = blockIdx.x * blockDim.x + threadIdx.x;
    if (i < 512)        g_bcat[i] = b_v[i];
    else if (i < 1024)  g_bcat[i] = b_m[i - 512];
    else if (i < 1536)  g_bcat[i] = b_q[i - 1024];
    else if (i < 1664)  g_bcat[i] = b_ke[i - 1536];
    else if (i < 1672)  g_bcat[i] = b_ve[i - 1664];
    else if (i == 1672) g_bcat[i] = b_g[0];
}

// ================= fp16 mma.sync GEMM (128x128 tile, 2-stage, 2 CTAs/SM) =================
// epi: 0 none, 2 exact gelu, 4 +eptr residual (fp32 out),
//      5 sincos(tanh*PI) -> half C, C2,
//      6 merged-proj (v1|mag|qd|ke-sincos|veg). ohalf: C as __half.
#define LDA_H 40
#define STAGE_H (256 * LDA_H)
__global__ void __launch_bounds__(256, 2) mma_gemm(
    const __half* __restrict__ A, const __half* __restrict__ WT,
    const float* __restrict__ bias,
    float* __restrict__ C, float* __restrict__ C2, float* __restrict__ C3,
    float* __restrict__ C4, float* __restrict__ C5,
    int K, int lda, int ldc, int epi, int ohalf, const float* __restrict__ eptr)
{
    extern __shared__ __half smh[];
    const int tid = threadIdx.x, wid = tid >> 5, lane = tid & 31;
    const int warp_m = wid & 3, warp_n = wid >> 2;
    const int n0 = blockIdx.x * 128, m0 = blockIdx.y * 128;
    const int NK = K >> 5;
    const int lq = lane >> 2, lr = lane & 3;

    const int g = lane >> 3, r = lane & 7;
    const uint32_t aoff = ((uint32_t)((warp_m * 32 + (g & 1) * 8 + r) * LDA_H
                           + (g >> 1) * 8)) * 2u;
    const uint32_t boff = ((uint32_t)((warp_n * 64 + (g >> 1) * 8 + r) * LDA_H
                           + (g & 1) * 8)) * 2u;

    const uint32_t sbase = smem_u32(smh);

    float c[2][8][4];
#pragma unroll
    for (int mi = 0; mi < 2; mi++)
#pragma unroll
        for (int j = 0; j < 8; j++)
#pragma unroll
            for (int q = 0; q < 4; q++) c[mi][j][q] = 0.f;

    auto load_tile = [&](int kt, int buf) {
        __half* dst = smh + buf * STAGE_H;
#pragma unroll
        for (int i = 0; i < 2; i++) {
            int idx = tid + i * 256;
            int row = idx >> 2, cq = idx & 3;
            cp16(smem_u32(dst + row * LDA_H + cq * 8),
                 A + (size_t)(m0 + row) * lda + kt * 32 + cq * 8);
        }
#pragma unroll
        for (int i = 0; i < 2; i++) {
            int idx = tid + i * 256;
            int row = idx >> 2, cq = idx & 3;
            cp16(smem_u32(dst + 128 * LDA_H + row * LDA_H + cq * 8),
                 WT + (size_t)(n0 + row) * K + kt * 32 + cq * 8);
        }
        CP_COMMIT();
    };

    load_tile(0, 0);

    for (int kt = 0; kt < NK; kt++) {
        int buf = kt & 1;
        if (kt + 1 < NK) load_tile(kt + 1, buf ^ 1);
        if (kt + 1 < NK) { CP_WAIT1(); } else { CP_WAIT0(); }
        __syncthreads();

        const uint32_t aBase = sbase + (uint32_t)(buf * STAGE_H) * 2u;
        const uint32_t bBase = aBase + 128u * LDA_H * 2u;
#pragma unroll
        for (int ks = 0; ks < 2; ks++) {
            uint32_t kbb = (uint32_t)ks * 32u;
            uint32_t a[2][4];
            ldmx4(a[0], aBase + aoff + kbb);
            ldmx4(a[1], aBase + aoff + 16u * LDA_H * 2u + kbb);
#pragma unroll
            for (int jp = 0; jp < 4; jp++) {
                uint32_t bR[4];
                ldmx4(bR, bBase + boff + (uint32_t)jp * 16u * LDA_H * 2u + kbb);
                int j0 = jp * 2;
                mma_f16(c[0][j0], a[0][0], a[0][1], a[0][2], a[0][3], bR[0], bR[1]);
                mma_f16(c[1][j0], a[1][0], a[1][1], a[1][2], a[1][3], bR[0], bR[1]);
                mma_f16(c[0][j0 + 1], a[0][0], a[0][1], a[0][2], a[0][3], bR[2], bR[3]);
                mma_f16(c[1][j0 + 1], a[1][0], a[1][1], a[1][2], a[1][3], bR[2], bR[3]);
            }
        }
        __syncthreads();
    }

    // ---------------- epilogue ----------------
    float scale1 = (epi == 6) ? fabsf(*eptr) : 0.f;
    int t = n0 >> 7;   // tile index for epi6
#pragma unroll
    for (int mi = 0; mi < 2; mi++) {
#pragma unroll
        for (int j = 0; j < 8; j++) {
            int gm = m0 + warp_m * 32 + mi * 16 + lq;
            int gn = n0 + warp_n * 64 + j * 8 + lr * 2;
            float b0 = bias[gn], b1 = bias[gn + 1];
#pragma unroll
            for (int h = 0; h < 2; h++) {
                int gmr = gm + h * 8;
                float v0 = c[mi][j][h * 2 + 0] + b0;
                float v1 = c[mi][j][h * 2 + 1] + b1;
                if (epi == 6) {
                    if (t < 4) {
                        __half* Ch = (__half*)C;
                        Ch[(size_t)gmr * 512 + gn] = __float2half_rn(v0);
                        Ch[(size_t)gmr * 512 + gn + 1] = __float2half_rn(v1);
                    } else if (t < 8) {
                        __half* Ch = (__half*)C2;
                        size_t oo = (size_t)gmr * 512 + gn - 512;
                        Ch[oo]     = __float2half_rn(scale1 / (1.f + expf(-v0)));
                        Ch[oo + 1] = __float2half_rn(scale1 / (1.f + expf(-v1)));
                    } else if (t < 12) {
                        __half* Ch = (__half*)C3;
                        size_t oo = (size_t)gmr * 512 + gn - 1024;
                        Ch[oo] = __float2half_rn(v0);
                        Ch[oo + 1] = __float2half_rn(v1);
                    } else if (t == 12) {
                        size_t oo = (size_t)gmr * 128 + gn - 1536;
                        float t0 = tanhf(v0) * PI_F, t1 = tanhf(v1) * PI_F;
                        float s0, cc0, s1, cc1;
                        sincosf(t0, &s0, &cc0);
                        sincosf(t1, &s1, &cc1);
                        __half* C4h = (__half*)C4;
                        __half* C5h = (__half*)C5;
                        C4h[oo] = __float2half_rn(cc0); C4h[oo + 1] = __float2half_rn(cc1);
                        C5h[oo] = __float2half_rn(s0);  C5h[oo + 1] = __float2half_rn(s1);
                    } else {
                        int col0 = gn - 1664;
                        if (col0 < 8) g_gvraw[(size_t)gmr * 8 + col0] = v0;
                        else if (col0 == 8) g_gate[gmr] = 1.f / (1.f + expf(-v0));
                        int col1 = col0 + 1;
                        if (col1 < 8) g_gvraw[(size_t)gmr * 8 + col1] = v1;
                        else if (col1 == 8) g_gate[gmr] = 1.f / (1.f + expf(-v1));
                    }
                    continue;
                }
                size_t oo = (size_t)gmr * ldc + gn;
                if (epi == 5) {
                    float t0 = tanhf(v0) * PI_F, t1 = tanhf(v1) * PI_F;
                    float s0, c0, s1, c1;
                    sincosf(t0, &s0, &c0);
                    sincosf(t1, &s1, &c1);
                    ((__half*)C)[oo]      = __float2half_rn(c0);
                    ((__half*)C)[oo + 1]  = __float2half_rn(c1);
                    ((__half*)C2)[oo]     = __float2half_rn(s0);
                    ((__half*)C2)[oo + 1] = __float2half_rn(s1);
                    continue;
                }
                if (epi == 2) {
                    v0 = 0.5f * v0 * (1.f + erff(v0 * 0.70710678118654752f));
                    v1 = 0.5f * v1 * (1.f + erff(v1 * 0.70710678118654752f));
                } else if (epi == 4) {
                    v0 += eptr[oo];
                    v1 += eptr[oo + 1];
                }
                if (ohalf) {
                    __half* Ch = (__half*)C;
                    Ch[oo] = __float2half_rn(v0);
                    Ch[oo + 1] = __float2half_rn(v1);
                } else {
                    C[oo] = v0; C[oo + 1] = v1;
                }
            }
        }
    }
}

// ================= context_avg scan (2-channel float2, 2-token unroll) =================
__global__ void ctx_p1(const float* __restrict__ x) {
    int bc = blockIdx.x; int b = bc >> NC_SH, c = bc & NC_MASK;
    int d2 = blockIdx.y * 128 + threadIdx.x;   // float2 index (0..255)
    const float2* xp = (const float2*)x + ((size_t)(b * Lv + c * LCv)) * 256 + d2;
    float s0 = 0.f, s1 = 0.f, t0 = 0.f, t1 = 0.f;
    for (int i = 0; i < LCv; i += 2) {
        float2 a = xp[(size_t)i * 256];
        float2 e = xp[(size_t)(i + 1) * 256];
        s0 += a.x; s1 += a.y;
        t0 += e.x; t1 += e.y;
    }
    ((float2*)g_pctx)[(size_t)bc * 256 + d2] = make_float2(s0 + t0, s1 + t1);
}
__global__ void ctx_p2() {
    int idx = blockIdx.x * blockDim.x + threadIdx.x;
    if (idx >= Bv * Dv) return;
    int b = idx / Dv, d = idx % Dv;
    float v[NCv];
#pragma unroll
    for (int c = 0; c < NCv; c++)
        v[c] = g_pctx[((size_t)(b * NCv + c)) * Dv + d];
    float run = 0.f;
#pragma unroll
    for (int c = 0; c < NCv; c++) { float t = v[c]; v[c] = run; run += t; }
#pragma unroll
    for (int c = 0; c < NCv; c++)
        g_pctx[((size_t)(b * NCv + c)) * Dv + d] = v[c];
}
__global__ void ctx_p3(const float* __restrict__ x) {
    int bc = blockIdx.x; int b = bc >> NC_SH, c = bc & NC_MASK;
    int d2 = blockIdx.y * 128 + threadIdx.x;
    const float2* xp = (const float2*)x + ((size_t)(b * Lv + c * LCv)) * 256 + d2;
    float2 s = ((const float2*)g_pctx)[(size_t)bc * 256 + d2];
    __half2* xc = (__half2*)g_xcath;
    for (int i = 0; i < LCv; i += 2) {
        float2 a = xp[(size_t)i * 256];
        float2 e = xp[(size_t)(i + 1) * 256];
        int l0 = c * LCv + i;
        size_t row0 = (size_t)(b * Lv + l0) * 512;
        s.x += a.x; s.y += a.y;
        float inv0 = 1.f / (float)(l0 + 1);
        xc[row0 + d2] = __floats2half2_rn(a.x, a.y);
        xc[row0 + 256 + d2] = __floats2half2_rn(s.x * inv0, s.y * inv0);
        size_t row1 = row0 + 512;
        s.x += e.x; s.y += e.y;
        float inv1 = 1.f / (float)(l0 + 2);
        xc[row1 + d2] = __floats2half2_rn(e.x, e.y);
        xc[row1 + 256 + d2] = __floats2half2_rn(s.x * inv1, s.y * inv1);
    }
}

// ================= mem1 scan + fused pos_ret (2-channel half2, 2-token unroll) =================
__global__ void mem1_p1(const float* __restrict__ pos) {
    int bc = blockIdx.x; int b = bc >> NC_SH, c = bc & NC_MASK;
    int d2 = blockIdx.y * 128 + threadIdx.x;
    size_t base2 = ((size_t)(b * Lv + c * LCv)) * 256 + d2;
    const __half2* magp = (const __half2*)g_magh;
    const __half2* v1p  = (const __half2*)g_v1h;
    const float2* posp  = (const float2*)pos;
    float sc0 = 0.f, ss0 = 0.f, sm0 = 0.f, sc1 = 0.f, ss1 = 0.f, sm1 = 0.f;
    for (int i = 0; i < LCv; i += 2) {
        __half2 m0 = magp[base2 + (size_t)i * 256];
        __half2 w0 = v1p[base2 + (size_t)i * 256];
        __half2 m1 = magp[base2 + (size_t)(i + 1) * 256];
        __half2 w1 = v1p[base2 + (size_t)(i + 1) * 256];
        int lg = c * LCv + i;
        float2 p0 = posp[(size_t)lg * 256 + d2];
        float2 p1 = posp[(size_t)(lg + 1) * 256 + d2];
        float2 mf = __half22float2(m0), vf = __half22float2(w0);
        float sphi, cphi;
        sincosf(p0.x, &sphi, &cphi);
        float wgt = mf.x * vf.x;
        sc0 += wgt * cphi; ss0 += wgt * sphi; sm0 += mf.x;
        sincosf(p0.y, &sphi, &cphi);
        wgt = mf.y * vf.y;
        sc1 += wgt * cphi; ss1 += wgt * sphi; sm1 += mf.y;
        mf = __half22float2(m1); vf = __half22float2(w1);
        sincosf(p1.x, &sphi, &cphi);
        wgt = mf.x * vf.x;
        sc0 += wgt * cphi; ss0 += wgt * sphi; sm0 += mf.x;
        sincosf(p1.y, &sphi, &cphi);
        wgt = mf.y * vf.y;
        sc1 += wgt * cphi; ss1 += wgt * sphi; sm1 += mf.y;
    }
    size_t o2 = (size_t)bc * 256 + d2;
    ((float2*)g_pmc)[o2] = make_float2(sc0, sc1);
    ((float2*)g_pms)[o2] = make_float2(ss0, ss1);
    ((float2*)g_pmm)[o2] = make_float2(sm0, sm1);
}
__global__ void mem1_p2() {
    int idx = blockIdx.x * blockDim.x + threadIdx.x;
    if (idx >= Bv * Dv) return;
    int sel = blockIdx.y;
    float* arr = (sel == 0) ? g_pmc : ((sel == 1) ? g_pms : g_pmm);
    int b = idx / Dv, d = idx % Dv;
    float v[NCv];
#pragma unroll
    for (int c = 0; c < NCv; c++)
        v[c] = arr[((size_t)(b * NCv + c)) * Dv + d];
    float run = 0.f;
#pragma unroll
    for (int c = 0; c < NCv; c++) { float t = v[c]; v[c] = run; run += t; }
#pragma unroll
    for (int c = 0; c < NCv; c++)
        arr[((size_t)(b * NCv + c)) * Dv + d] = v[c];
}
__global__ void mem1_p3(const float* __restrict__ pos) {
    int bc = blockIdx.x; int b = bc >> NC_SH, c = bc & NC_MASK;
    int d2 = blockIdx.y * 128 + threadIdx.x;
    size_t base2 = ((size_t)(b * Lv + c * LCv)) * 256 + d2;
    size_t po2 = (size_t)bc * 256 + d2;
    const __half2* magp = (const __half2*)g_magh;
    const __half2* v1p  = (const __half2*)g_v1h;
    const __half2* qdp  = (const __half2*)g_qdh;
    const float2* posp  = (const float2*)pos;
    __half2* outp = (__half2*)g_posreth;
    float2 scv = ((const float2*)g_pmc)[po2];
    float2 ssv = ((const float2*)g_pms)[po2];
    float2 smv = ((const float2*)g_pmm)[po2];
    for (int i = 0; i < LCv; i += 2) {
        __half2 m0 = magp[base2 + (size_t)i * 256];
        __half2 w0 = v1p[base2 + (size_t)i * 256];
        __half2 q0 = qdp[base2 + (size_t)i * 256];
        __half2 m1 = magp[base2 + (size_t)(i + 1) * 256];
        __half2 w1 = v1p[base2 + (size_t)(i + 1) * 256];
        __half2 q1 = qdp[base2 + (size_t)(i + 1) * 256];
        int lg = c * LCv + i;
        float2 p0 = posp[(size_t)lg * 256 + d2];
        float2 p1 = posp[(size_t)(lg + 1) * 256 + d2];
#pragma unroll
        for (int u = 0; u < 2; u++) {
            float2 mf = __half22float2(u ? m1 : m0);
            float2 vf = __half22float2(u ? w1 : w0);
            float2 qf = __half22float2(u ? q1 : q0);
            float2 pp = u ? p1 : p0;
            float sphi, cphi, sq, cq;
            // channel x
            sincosf(pp.x, &sphi, &cphi);
            float wgt = mf.x * vf.x;
            scv.x += wgt * cphi; ssv.x += wgt * sphi; smv.x += mf.x;
            sincosf(pp.x + qf.x, &sq, &cq);
            float r0 = (scv.x * cq + ssv.x * sq) * rsqrtf(smv.x + 1e-8f) * INV_SQRT_D;
            // channel y
            sincosf(pp.y, &sphi, &cphi);
            wgt = mf.y * vf.y;
            scv.y += wgt * cphi; ssv.y += wgt * sphi; smv.y += mf.y;
            sincosf(pp.y + qf.y, &sq, &cq);
            float r1 = (scv.y * cq + ssv.y * sq) * rsqrtf(smv.y + 1e-8f) * INV_SQRT_D;
            outp[base2 + (size_t)(i + u) * 256] = __floats2half2_rn(r0, r1);
        }
    }
}

// ================= kv phasor scan: 8-token chunked, warp-per-v =================
__global__ void __launch_bounds__(256) kv_p1() {
    __shared__ float s_csp[8][128], s_ssp[8][128];
    __shared__ float s_gv[8][8], s_gate[8];
    int bc = blockIdx.x; int b = bc >> NC_SH, c = bc & NC_MASK;
    int tid = threadIdx.x, w = tid >> 5, l = tid & 31;
    int mbase = b * Lv + c * LCv;
    float aC[4] = {0, 0, 0, 0}, aS[4] = {0, 0, 0, 0};
    float gs = 0.f;
    for (int r0 = 0; r0 < LCv; r0 += 8) {
#pragma unroll
        for (int e = tid; e < 1024; e += 256) {
            int i = e >> 7, p = e & 127;
            size_t mm = (size_t)(mbase + r0 + i) * 128 + p;
            s_csp[i][p] = __half2float(g_csph[mm]);
            s_ssp[i][p] = __half2float(g_ssph[mm]);
        }
        if (tid < 64) s_gv[tid >> 3][tid & 7] = g_gvraw[(size_t)(mbase + r0 + (tid >> 3)) * 8 + (tid & 7)];
        if (tid < 8) s_gate[tid] = g_gate[mbase + r0 + tid];
        __syncthreads();
#pragma unroll
        for (int i = 0; i < 8; i++) {
            float gvv = s_gv[i][w] * s_gate[i];
            float4 cv = ((const float4*)s_csp[i])[l];
            float4 sv = ((const float4*)s_ssp[i])[l];
            aC[0] += cv.x * gvv; aC[1] += cv.y * gvv;
            aC[2] += cv.z * gvv; aC[3] += cv.w * gvv;
            aS[0] += sv.x * gvv; aS[1] += sv.y * gvv;
            aS[2] += sv.z * gvv; aS[3] += sv.w * gvv;
            gs += s_gate[i];
        }
        __syncthreads();
    }
#pragma unroll
    for (int j = 0; j < 4; j++) {
        size_t o = (size_t)bc * 1024 + (size_t)(4 * l + j) * 8 + w;
        g_pkc[o] = aC[j]; g_pks[o] = aS[j];
    }
    if (tid == 0) g_pg[bc] = gs;
}
__global__ void kv_p2() {
    int idx = blockIdx.x * blockDim.x + threadIdx.x;
    if (idx < Bv * Pv * Vv) {
        float* arr = blockIdx.y ? g_pks : g_pkc;
        int b = idx >> 10, pv = idx & 1023;
        float v[NCv];
#pragma unroll
        for (int c = 0; c < NCv; c++)
            v[c] = arr[((size_t)(b * NCv + c)) * 1024 + pv];
        float run = 0.f;
#pragma unroll
        for (int c = 0; c < NCv; c++) { float t = v[c]; v[c] = run; run += t; }
#pragma unroll
        for (int c = 0; c < NCv; c++)
            arr[((size_t)(b * NCv + c)) * 1024 + pv] = v[c];
    }
    if (blockIdx.x == 0 && blockIdx.y == 0 && idx < Bv) {
        float v[NCv];
#pragma unroll
        for (int c = 0; c < NCv; c++) v[c] = g_pg[(size_t)idx * NCv + c];
        float run = 0.f;
#pragma unroll
        for (int c = 0; c < NCv; c++) { float t = v[c]; v[c] = run; run += t; }
#pragma unroll
        for (int c = 0; c < NCv; c++) g_pg[(size_t)idx * NCv + c] = v[c];
    }
}
__global__ void __launch_bounds__(256) kv_p3(
    const float* __restrict__ w_kv, const float* __restrict__ b_kv)
{
    __shared__ float s_csp[8][128], s_ssp[8][128], s_cqp[8][128], s_sqp[8][128];
    __shared__ float s_gv[8][8], s_gate[8], s_kvr[8][8];
    __shared__ float s_wkv[8 * 512];
    __shared__ float s_bkv[512];
    int bc = blockIdx.x; int b = bc >> NC_SH, c = bc & NC_MASK;
    int tid = threadIdx.x, w = tid >> 5, l = tid & 31;
    int mbase = b * Lv + c * LCv;
    for (int i = tid; i < 8 * 512; i += 256) s_wkv[i] = w_kv[i];
    for (int i = tid; i < 512; i += 256) s_bkv[i] = b_kv[i];
    float aC[4], aS[4];
#pragma unroll
    for (int j = 0; j < 4; j++) {
        size_t o = (size_t)bc * 1024 + (size_t)(4 * l + j) * 8 + w;
        aC[j] = g_pkc[o]; aS[j] = g_pks[o];
    }
    float gsum = g_pg[bc];
    for (int r0 = 0; r0 < LCv; r0 += 8) {
#pragma unroll
        for (int e = tid; e < 1024; e += 256) {
            int i = e >> 7, p = e & 127;
            size_t mm = (size_t)(mbase + r0 + i) * 128 + p;
            s_csp[i][p] = __half2float(g_csph[mm]);
            s_ssp[i][p] = __half2float(g_ssph[mm]);
            s_cqp[i][p] = __half2float(g_cqph[mm]);
            s_sqp[i][p] = __half2float(g_sqph[mm]);
        }
        if (tid < 64) s_gv[tid >> 3][tid & 7] = g_gvraw[(size_t)(mbase + r0 + (tid >> 3)) * 8 + (tid & 7)];
        if (tid < 8) s_gate[tid] = g_gate[mbase + r0 + tid];
        __syncthreads();
#pragma unroll
        for (int i = 0; i < 8; i++) {
            float gvv = s_gv[i][w] * s_gate[i];
            float4 cv = ((const float4*)s_csp[i])[l];
            float4 sv = ((const float4*)s_ssp[i])[l];
            float4 cq = ((const float4*)s_cqp[i])[l];
            float4 sq = ((const float4*)s_sqp[i])[l];
            aC[0] += cv.x * gvv; aS[0] += sv.x * gvv;
            aC[1] += cv.y * gvv; aS[1] += sv.y * gvv;
            aC[2] += cv.z * gvv; aS[2] += sv.z * gvv;
            aC[3] += cv.w * gvv; aS[3] += sv.w * gvv;
            float pr = cq.x * aC[0] + sq.x * aS[0]
                     + cq.y * aC[1] + sq.y * aS[1]
                     + cq.z * aC[2] + sq.z * aS[2]
                     + cq.w * aC[3] + sq.w * aS[3];
#pragma unroll
            for (int o = 16; o; o >>= 1)
                pr += __shfl_xor_sync(0xffffffffu, pr, o);
            gsum += s_gate[i];
            if (l == 0)
                s_kvr[i][w] = pr * rsqrtf(fmaxf(gsum, 1.0f)) * INV_SQRT_P;
        }
        __syncthreads();
#pragma unroll
        for (int k = 0; k < 16; k++) {
            int idx = tid + k * 256;
            int tok = idx >> 9, n = idx & 511;
            float o = s_bkv[n];
#pragma unroll
            for (int v = 0; v < 8; v++)
                o += s_kvr[tok][v] * s_wkv[v * 512 + n];
            g_ccath[(size_t)(mbase + r0 + tok) * 1024 + 512 + n] = __float2half_rn(o);
        }
        __syncthreads();
    }
}

// ================= LayerNorm (half in/out) =================
__global__ void __launch_bounds__(256) ln_kernel(
    const float* __restrict__ lng, const float* __restrict__ lnb)
{
    int m = blockIdx.x, tid = threadIdx.x;
    const __half2* row = (const __half2*)(g_ccath + (size_t)m * 1024);
    __half2 h0 = row[tid * 2], h1 = row[tid * 2 + 1];
    float2 f0 = __half22float2(h0), f1 = __half22float2(h1);
    float s = f0.x + f0.y + f1.x + f1.y;
    float q = f0.x * f0.x + f0.y * f0.y + f1.x * f1.x + f1.y * f1.y;
#pragma unroll
    for (int o = 16; o; o >>= 1) {
        s += __shfl_xor_sync(0xffffffffu, s, o);
        q += __shfl_xor_sync(0xffffffffu, q, o);
    }
    __shared__ float ss[8], sq[8];
    __shared__ float smu, srs;
    if ((tid & 31) == 0) { ss[tid >> 5] = s; sq[tid >> 5] = q; }
    __syncthreads();
    if (tid == 0) {
        float S = 0.f, Q = 0.f;
#pragma unroll
        for (int w = 0; w < 8; w++) { S += ss[w]; Q += sq[w]; }
        float mu = S * (1.f / 1024.f);
        float var = Q * (1.f / 1024.f) - mu * mu;
        smu = mu; srs = rsqrtf(var + 1e-5f);
    }
    __syncthreads();
    float mu = smu, rs = srs;
    float4 g4 = ((const float4*)lng)[tid];
    float4 b4 = ((const float4*)lnb)[tid];
    __half2* oh = (__half2*)(g_lnh + (size_t)m * 1024);
    oh[tid * 2]     = __floats2half2_rn((f0.x - mu) * rs * g4.x + b4.x,
                                        (f0.y - mu) * rs * g4.y + b4.y);
    oh[tid * 2 + 1] = __floats2half2_rn((f1.x - mu) * rs * g4.z + b4.z,
                                        (f1.y - mu) * rs * g4.w + b4.w);
}

// ================= launch =================
extern "C" void kernel_launch(void* const* d_in, const int* in_sizes, int n_in,
                              void* d_out, int out_size)
{
    const float* x    = (const float*)d_in[0];
    const float* pos  = (const float*)d_in[1];
    const float* ms   = (const float*)d_in[2];
    const float* w_v  = (const float*)d_in[3];
    const float* b_v  = (const float*)d_in[4];
    const float* w_o  = (const float*)d_in[5];
    const float* b_o  = (const float*)d_in[6];
    const float* w_m  = (const float*)d_in[7];
    const float* b_m  = (const float*)d_in[8];
    const float* w_q  = (const float*)d_in[9];
    const float* b_q  = (const float*)d_in[10];
    const float* w_ke = (const float*)d_in[11];
    const float* b_ke = (const float*)d_in[12];
    const float* w_ve = (const float*)d_in[13];
    const float* b_ve = (const float*)d_in[14];
    const float* w_s1 = (const float*)d_in[15];
    const float* b_s1 = (const float*)d_in[16];
    const float* w_s2 = (const float*)d_in[17];
    const float* b_s2 = (const float*)d_in[18];
    const float* w_g  = (const float*)d_in[19];
    const float* b_g  = (const float*)d_in[20];
    const float* w_kv = (const float*)d_in[21];
    const float* b_kv = (const float*)d_in[22];
    const float* lng  = (const float*)d_in[23];
    const float* lnb  = (const float*)d_in[24];
    const float* w_t1 = (const float*)d_in[25];
    const float* b_t1 = (const float*)d_in[26];
    const float* w_t2 = (const float*)d_in[27];
    const float* b_t2 = (const float*)d_in[28];
    float* out = (float*)d_out;

    float *p_bcat;
    __half *p_wth, *p_xcath, *p_v1h, *p_magh, *p_qdh, *p_cqph, *p_sqph,
           *p_csph, *p_ssph, *p_s1gh, *p_posreth, *p_ccath, *p_lnh, *p_h1h;
    cudaGetSymbolAddress((void**)&p_bcat, g_bcat);
    cudaGetSymbolAddress((void**)&p_wth, g_wth);
    cudaGetSymbolAddress((void**)&p_xcath, g_xcath);
    cudaGetSymbolAddress((void**)&p_v1h, g_v1h);
    cudaGetSymbolAddress((void**)&p_magh, g_magh);
    cudaGetSymbolAddress((void**)&p_qdh, g_qdh);
    cudaGetSymbolAddress((void**)&p_cqph, g_cqph);
    cudaGetSymbolAddress((void**)&p_sqph, g_sqph);
    cudaGetSymbolAddress((void**)&p_csph, g_csph);
    cudaGetSymbolAddress((void**)&p_ssph, g_ssph);
    cudaGetSymbolAddress((void**)&p_s1gh, g_s1gh);
    cudaGetSymbolAddress((void**)&p_posreth, g_posreth);
    cudaGetSymbolAddress((void**)&p_ccath, g_ccath);
    cudaGetSymbolAddress((void**)&p_lnh, g_lnh);
    cudaGetSymbolAddress((void**)&p_h1h, g_h1h);

    __half* wt_proj = p_wth + WT_PROJ;
    __half* wt_o    = p_wth + WT_O;
    __half* wt_s1   = p_wth + WT_S1;
    __half* wt_s2   = p_wth + WT_S2;
    __half* wt_t1   = p_wth + WT_T1;
    __half* wt_t2   = p_wth + WT_T2;

    const int SMEM = 2 * STAGE_H * 2;  // 40960 B
    cudaFuncSetAttribute(mma_gemm, cudaFuncAttributeMaxDynamicSharedMemorySize, SMEM);

    TTable tt;
    tt.src[0] = w_v;  tt.dst[0] = wt_proj;              tt.K[0] = 512;  tt.N[0] = 512;
    tt.src[1] = w_m;  tt.dst[1] = wt_proj + 512 * 512;  tt.K[1] = 512;  tt.N[1] = 512;
    tt.src[2] = w_q;  tt.dst[2] = wt_proj + 1024 * 512; tt.K[2] = 512;  tt.N[2] = 512;
    tt.src[3] = w_ke; tt.dst[3] = wt_proj + 1536 * 512; tt.K[3] = 512;  tt.N[3] = 128;
    tt.src[4] = w_o;  tt.dst[4] = wt_o;                 tt.K[4] = 512;  tt.N[4] = 512;
    tt.src[5] = w_s1; tt.dst[5] = wt_s1;                tt.K[5] = 1024; tt.N[5] = 512;
    tt.src[6] = w_s2; tt.dst[6] = wt_s2;                tt.K[6] = 512;  tt.N[6] = 128;
    tt.src[7] = w_t1; tt.dst[7] = wt_t1;                tt.K[7] = 1024; tt.N[7] = 1024;
    tt.src[8] = w_t2; tt.dst[8] = wt_t2;                tt.K[8] = 1024; tt.N[8] = 512;
    int acc = 0;
    for (int i = 0; i < 9; i++) {
        tt.t0[i] = acc;
        acc += (tt.K[i] >> 5) * (tt.N[i] >> 5);
    }
    transpose_all<<<acc, 256>>>(tt);
    pack_veg<<<18, 256>>>(w_ve, w_g);
    bias_concat<<<7, 256>>>(b_v, b_m, b_q, b_ke, b_ve, b_g);

    dim3 tb(256);
    dim3 gScan2(Bv * NCv, 2);

    ctx_p1<<<gScan2, 128>>>(x);
    ctx_p2<<<(Bv * Dv + 255) / 256, 256>>>();
    ctx_p3<<<gScan2, 128>>>(x);

    // merged projections: v | mag | qd | ke-sincos | ve+gate
    mma_gemm<<<dim3(14, 128), tb, SMEM>>>(p_xcath, wt_proj, p_bcat,
        (float*)p_v1h, (float*)p_magh, (float*)p_qdh,
        (float*)p_cqph, (float*)p_sqph, 512, 1024, 512, 6, 0, ms);
    mma_gemm<<<dim3(4, 128), tb, SMEM>>>(p_xcath, wt_s1, b_s1,
        (float*)p_s1gh, nullptr, nullptr, nullptr, nullptr, 1024, 1024, 512, 2, 1, nullptr);
    mma_gemm<<<dim3(1, 128), tb, SMEM>>>(p_s1gh, wt_s2, b_s2,
        (float*)p_csph, (float*)p_ssph, nullptr, nullptr, nullptr, 512, 512, 128, 5, 0, nullptr);

    // mem1 scan + pos_out
    mem1_p1<<<gScan2, 128>>>(pos);
    mem1_p2<<<dim3((Bv * Dv + 255) / 256, 3), 256>>>();
    mem1_p3<<<gScan2, 128>>>(pos);
    mma_gemm<<<dim3(4, 128), tb, SMEM>>>(p_posreth, wt_o, b_o,
        (float*)p_ccath, nullptr, nullptr, nullptr, nullptr, 512, 512, 1024, 0, 1, nullptr);

    // kv scan + retrieval + fused kv_out
    kv_p1<<<Bv * NCv, 256>>>();
    kv_p2<<<dim3((Bv * Pv * Vv + 255) / 256, 2), 256>>>();
    kv_p3<<<Bv * NCv, 256>>>(w_kv, b_kv);

    // LN + output MLP + residual
    ln_kernel<<<Mv, 256>>>(lng, lnb);
    mma_gemm<<<dim3(8, 128), tb, SMEM>>>(p_lnh, wt_t1, b_t1,
        (float*)p_h1h, nullptr, nullptr, nullptr, nullptr, 1024, 1024, 1024, 2, 1, nullptr);
    mma_gemm<<<dim3(4, 128), tb, SMEM>>>(p_h1h, wt_t2, b_t2,
        out, nullptr, nullptr, nullptr, nullptr, 1024, 1024, 512, 4, 0, x);
}

// round 16
// speedup vs baseline: 1.2067x; 1.1485x over previous
#include <cuda_runtime.h>
#include <cuda_fp16.h>
#include <math.h>
#include <stdint.h>

#define Bv 4
#define Lv 4096
#define Dv 512
#define Pv 128
#define Vv 8
#define Mv (Bv*Lv)          // 16384
#define NCv 64
#define NC_SH 6
#define NC_MASK 63
#define LCv (Lv/NCv)        // 64
#define PI_F 3.14159265358979323846f
#define INV_SQRT_D 0.044194173824159216f
#define INV_SQRT_P 0.08838834764831845f

// ================= helpers =================
__device__ __forceinline__ uint32_t smem_u32(const void* p) {
    uint32_t a;
    asm("{ .reg .u64 t; cvta.to.shared.u64 t, %1; cvt.u32.u64 %0, t; }" : "=r"(a) : "l"(p));
    return a;
}
__device__ __forceinline__ void cp16(uint32_t s, const void* g) {
    asm volatile("cp.async.cg.shared.global [%0], [%1], 16;" :: "r"(s), "l"(g) : "memory");
}
#define CP_COMMIT() asm volatile("cp.async.commit_group;" ::: "memory")
#define CP_WAIT1()  asm volatile("cp.async.wait_group 1;" ::: "memory")
#define CP_WAIT0()  asm volatile("cp.async.wait_group 0;" ::: "memory")

__device__ __forceinline__ void mma_f16(float* c,
    uint32_t a0, uint32_t a1, uint32_t a2, uint32_t a3,
    uint32_t b0, uint32_t b1)
{
    asm volatile(
        "mma.sync.aligned.m16n8k16.row.col.f32.f16.f16.f32 "
        "{%0,%1,%2,%3}, {%4,%5,%6,%7}, {%8,%9}, {%0,%1,%2,%3};"
        : "+f"(c[0]), "+f"(c[1]), "+f"(c[2]), "+f"(c[3])
        : "r"(a0), "r"(a1), "r"(a2), "r"(a3), "r"(b0), "r"(b1));
}
__device__ __forceinline__ void ldmx4(uint32_t* r, uint32_t addr) {
    asm volatile(
        "ldmatrix.sync.aligned.m8n8.x4.shared.b16 {%0,%1,%2,%3}, [%4];"
        : "=r"(r[0]), "=r"(r[1]), "=r"(r[2]), "=r"(r[3]) : "r"(addr));
}

// ================= scratch =================
__device__ float g_gate[Mv], g_gvraw[(size_t)Mv*8];
__device__ float g_bcat[1792];
__device__ float g_pctx[Bv*NCv*Dv];
__device__ float g_pmc[Bv*NCv*Dv], g_pms[Bv*NCv*Dv], g_pmm[Bv*NCv*Dv];
__device__ float g_pkc[Bv*NCv*Pv*Vv], g_pks[Bv*NCv*Pv*Vv], g_pg[Bv*NCv];
// fp16 tensors
__device__ __half g_wth[3407872];
__device__ __half g_xcath[(size_t)Mv*1024];
__device__ __half g_v1h[(size_t)Mv*512], g_magh[(size_t)Mv*512], g_qdh[(size_t)Mv*512];
__device__ __half g_cqph[(size_t)Mv*128], g_sqph[(size_t)Mv*128];
__device__ __half g_csph[(size_t)Mv*128], g_ssph[(size_t)Mv*128];
__device__ __half g_s1gh[(size_t)Mv*512];
__device__ __half g_posreth[(size_t)Mv*512];
__device__ __half g_ccath[(size_t)Mv*1024];
__device__ __half g_lnh[(size_t)Mv*1024];
__device__ __half g_h1h[(size_t)Mv*1024];

// arena offsets (halves)
#define WT_PROJ 0           // 1792 x 512
#define WT_O    917504
#define WT_S1   1179648
#define WT_S2   1703936
#define WT_T1   1769472
#define WT_T2   2818048

// ================= batched transpose -> fp16 =================
struct TTable {
    const float* src[9];
    __half* dst[9];
    int K[9], N[9], t0[9];
};
__global__ void __launch_bounds__(256) transpose_all(TTable tt) {
    __shared__ float t[32][33];
    int bid = blockIdx.x;
    int w = 8;
#pragma unroll
    for (int i = 8; i >= 0; i--) if (bid >= tt.t0[i]) { w = i; break; }
    int tl = bid - tt.t0[w];
    int K = tt.K[w], N = tt.N[w];
    int tilesK = K >> 5;
    int k0 = (tl % tilesK) * 32, n0 = (tl / tilesK) * 32;
    const float* W = tt.src[w];
    __half* WT = tt.dst[w];
    int tx = threadIdx.x & 31, ty = threadIdx.x >> 5;
#pragma unroll
    for (int i = ty; i < 32; i += 8) t[i][tx] = W[(size_t)(k0 + i) * N + n0 + tx];
    __syncthreads();
#pragma unroll
    for (int i = ty; i < 32; i += 8)
        WT[(size_t)(n0 + i) * K + k0 + tx] = __float2half_rn(t[tx][i]);
}

// pack w_ve (512x8) and w_g (512x1) into proj arena rows 1664..1672
__global__ void pack_veg(const float* __restrict__ w_ve, const float* __restrict__ w_g) {
    int idx = blockIdx.x * blockDim.x + threadIdx.x;
    if (idx < 4096) {
        int k = idx >> 3, v = idx & 7;
        g_wth[WT_PROJ + (size_t)(1664 + v) * 512 + k] = __float2half_rn(w_ve[k * 8 + v]);
    } else if (idx < 4608) {
        int k = idx - 4096;
        g_wth[WT_PROJ + (size_t)1672 * 512 + k] = __float2half_rn(w_g[k]);
    }
}

// ================= bias concat =================
__global__ void bias_concat(const float* b_v, const float* b_m,
                            const float* b_q, const float* b_ke,
                            const float* b_ve, const float* b_g) {
    int i = blockIdx.x * blockDim.x + threadIdx.x;
    if (i < 512)        g_bcat[i] = b_v[i];
    else if (i < 1024)  g_bcat[i] = b_m[i - 512];
    else if (i < 1536)  g_bcat[i] = b_q[i - 1024];
    else if (i < 1664)  g_bcat[i] = b_ke[i - 1536];
    else if (i < 1672)  g_bcat[i] = b_ve[i - 1664];
    else if (i == 1672) g_bcat[i] = b_g[0];
}

// ================= fp16 mma.sync GEMM (128x128 tile, 2-stage, 2 CTAs/SM) =================
// epi: 0 none, 2 exact gelu, 4 +eptr residual (fp32 out),
//      5 sincos(tanh*PI) -> half C, C2,
//      6 merged-proj (v1|mag|qd|ke-sincos|veg). ohalf: C as __half.
#define LDA_H 40
#define STAGE_H (256 * LDA_H)
__global__ void __launch_bounds__(256, 2) mma_gemm(
    const __half* __restrict__ A, const __half* __restrict__ WT,
    const float* __restrict__ bias,
    float* __restrict__ C, float* __restrict__ C2, float* __restrict__ C3,
    float* __restrict__ C4, float* __restrict__ C5,
    int K, int lda, int ldc, int epi, int ohalf, const float* __restrict__ eptr)
{
    extern __shared__ __half smh[];
    const int tid = threadIdx.x, wid = tid >> 5, lane = tid & 31;
    const int warp_m = wid & 3, warp_n = wid >> 2;
    const int n0 = blockIdx.x * 128, m0 = blockIdx.y * 128;
    const int NK = K >> 5;
    const int lq = lane >> 2, lr = lane & 3;

    const int g = lane >> 3, r = lane & 7;
    const uint32_t aoff = ((uint32_t)((warp_m * 32 + (g & 1) * 8 + r) * LDA_H
                           + (g >> 1) * 8)) * 2u;
    const uint32_t boff = ((uint32_t)((warp_n * 64 + (g >> 1) * 8 + r) * LDA_H
                           + (g & 1) * 8)) * 2u;

    const uint32_t sbase = smem_u32(smh);

    float c[2][8][4];
#pragma unroll
    for (int mi = 0; mi < 2; mi++)
#pragma unroll
        for (int j = 0; j < 8; j++)
#pragma unroll
            for (int q = 0; q < 4; q++) c[mi][j][q] = 0.f;

    auto load_tile = [&](int kt, int buf) {
        __half* dst = smh + buf * STAGE_H;
#pragma unroll
        for (int i = 0; i < 2; i++) {
            int idx = tid + i * 256;
            int row = idx >> 2, cq = idx & 3;
            cp16(smem_u32(dst + row * LDA_H + cq * 8),
                 A + (size_t)(m0 + row) * lda + kt * 32 + cq * 8);
        }
#pragma unroll
        for (int i = 0; i < 2; i++) {
            int idx = tid + i * 256;
            int row = idx >> 2, cq = idx & 3;
            cp16(smem_u32(dst + 128 * LDA_H + row * LDA_H + cq * 8),
                 WT + (size_t)(n0 + row) * K + kt * 32 + cq * 8);
        }
        CP_COMMIT();
    };

    load_tile(0, 0);

    for (int kt = 0; kt < NK; kt++) {
        int buf = kt & 1;
        if (kt + 1 < NK) load_tile(kt + 1, buf ^ 1);
        if (kt + 1 < NK) { CP_WAIT1(); } else { CP_WAIT0(); }
        __syncthreads();

        const uint32_t aBase = sbase + (uint32_t)(buf * STAGE_H) * 2u;
        const uint32_t bBase = aBase + 128u * LDA_H * 2u;
#pragma unroll
        for (int ks = 0; ks < 2; ks++) {
            uint32_t kbb = (uint32_t)ks * 32u;
            uint32_t a[2][4];
            ldmx4(a[0], aBase + aoff + kbb);
            ldmx4(a[1], aBase + aoff + 16u * LDA_H * 2u + kbb);
#pragma unroll
            for (int jp = 0; jp < 4; jp++) {
                uint32_t bR[4];
                ldmx4(bR, bBase + boff + (uint32_t)jp * 16u * LDA_H * 2u + kbb);
                int j0 = jp * 2;
                mma_f16(c[0][j0], a[0][0], a[0][1], a[0][2], a[0][3], bR[0], bR[1]);
                mma_f16(c[1][j0], a[1][0], a[1][1], a[1][2], a[1][3], bR[0], bR[1]);
                mma_f16(c[0][j0 + 1], a[0][0], a[0][1], a[0][2], a[0][3], bR[2], bR[3]);
                mma_f16(c[1][j0 + 1], a[1][0], a[1][1], a[1][2], a[1][3], bR[2], bR[3]);
            }
        }
        __syncthreads();
    }

    // ---------------- epilogue ----------------
    float scale1 = (epi == 6) ? fabsf(*eptr) : 0.f;
    int t = n0 >> 7;   // tile index for epi6
#pragma unroll
    for (int mi = 0; mi < 2; mi++) {
#pragma unroll
        for (int j = 0; j < 8; j++) {
            int gm = m0 + warp_m * 32 + mi * 16 + lq;
            int gn = n0 + warp_n * 64 + j * 8 + lr * 2;
            float b0 = bias[gn], b1 = bias[gn + 1];
#pragma unroll
            for (int h = 0; h < 2; h++) {
                int gmr = gm + h * 8;
                float v0 = c[mi][j][h * 2 + 0] + b0;
                float v1 = c[mi][j][h * 2 + 1] + b1;
                if (epi == 6) {
                    if (t < 4) {
                        __half* Ch = (__half*)C;
                        Ch[(size_t)gmr * 512 + gn] = __float2half_rn(v0);
                        Ch[(size_t)gmr * 512 + gn + 1] = __float2half_rn(v1);
                    } else if (t < 8) {
                        __half* Ch = (__half*)C2;
                        size_t oo = (size_t)gmr * 512 + gn - 512;
                        Ch[oo]     = __float2half_rn(scale1 / (1.f + expf(-v0)));
                        Ch[oo + 1] = __float2half_rn(scale1 / (1.f + expf(-v1)));
                    } else if (t < 12) {
                        __half* Ch = (__half*)C3;
                        size_t oo = (size_t)gmr * 512 + gn - 1024;
                        Ch[oo] = __float2half_rn(v0);
                        Ch[oo + 1] = __float2half_rn(v1);
                    } else if (t == 12) {
                        size_t oo = (size_t)gmr * 128 + gn - 1536;
                        float t0 = tanhf(v0) * PI_F, t1 = tanhf(v1) * PI_F;
                        float s0, cc0, s1, cc1;
                        sincosf(t0, &s0, &cc0);
                        sincosf(t1, &s1, &cc1);
                        __half* C4h = (__half*)C4;
                        __half* C5h = (__half*)C5;
                        C4h[oo] = __float2half_rn(cc0); C4h[oo + 1] = __float2half_rn(cc1);
                        C5h[oo] = __float2half_rn(s0);  C5h[oo + 1] = __float2half_rn(s1);
                    } else {
                        int col0 = gn - 1664;
                        if (col0 < 8) g_gvraw[(size_t)gmr * 8 + col0] = v0;
                        else if (col0 == 8) g_gate[gmr] = 1.f / (1.f + expf(-v0));
                        int col1 = col0 + 1;
                        if (col1 < 8) g_gvraw[(size_t)gmr * 8 + col1] = v1;
                        else if (col1 == 8) g_gate[gmr] = 1.f / (1.f + expf(-v1));
                    }
                    continue;
                }
                size_t oo = (size_t)gmr * ldc + gn;
                if (epi == 5) {
                    float t0 = tanhf(v0) * PI_F, t1 = tanhf(v1) * PI_F;
                    float s0, c0, s1, c1;
                    sincosf(t0, &s0, &c0);
                    sincosf(t1, &s1, &c1);
                    ((__half*)C)[oo]      = __float2half_rn(c0);
                    ((__half*)C)[oo + 1]  = __float2half_rn(c1);
                    ((__half*)C2)[oo]     = __float2half_rn(s0);
                    ((__half*)C2)[oo + 1] = __float2half_rn(s1);
                    continue;
                }
                if (epi == 2) {
                    v0 = 0.5f * v0 * (1.f + erff(v0 * 0.70710678118654752f));
                    v1 = 0.5f * v1 * (1.f + erff(v1 * 0.70710678118654752f));
                } else if (epi == 4) {
                    v0 += eptr[oo];
                    v1 += eptr[oo + 1];
                }
                if (ohalf) {
                    __half* Ch = (__half*)C;
                    Ch[oo] = __float2half_rn(v0);
                    Ch[oo + 1] = __float2half_rn(v1);
                } else {
                    C[oo] = v0; C[oo + 1] = v1;
                }
            }
        }
    }
}

// ================= context_avg scan (2-channel float2, 2-token unroll) =================
__global__ void ctx_p1(const float* __restrict__ x) {
    int bc = blockIdx.x; int b = bc >> NC_SH, c = bc & NC_MASK;
    int d2 = blockIdx.y * 128 + threadIdx.x;
    const float2* xp = (const float2*)x + ((size_t)(b * Lv + c * LCv)) * 256 + d2;
    float s0 = 0.f, s1 = 0.f, t0 = 0.f, t1 = 0.f;
    for (int i = 0; i < LCv; i += 2) {
        float2 a = xp[(size_t)i * 256];
        float2 e = xp[(size_t)(i + 1) * 256];
        s0 += a.x; s1 += a.y;
        t0 += e.x; t1 += e.y;
    }
    ((float2*)g_pctx)[(size_t)bc * 256 + d2] = make_float2(s0 + t0, s1 + t1);
}
__global__ void ctx_p2() {
    int idx = blockIdx.x * blockDim.x + threadIdx.x;
    if (idx >= Bv * Dv) return;
    int b = idx / Dv, d = idx % Dv;
    float v[NCv];
#pragma unroll
    for (int c = 0; c < NCv; c++)
        v[c] = g_pctx[((size_t)(b * NCv + c)) * Dv + d];
    float run = 0.f;
#pragma unroll
    for (int c = 0; c < NCv; c++) { float t = v[c]; v[c] = run; run += t; }
#pragma unroll
    for (int c = 0; c < NCv; c++)
        g_pctx[((size_t)(b * NCv + c)) * Dv + d] = v[c];
}
__global__ void ctx_p3(const float* __restrict__ x) {
    int bc = blockIdx.x; int b = bc >> NC_SH, c = bc & NC_MASK;
    int d2 = blockIdx.y * 128 + threadIdx.x;
    const float2* xp = (const float2*)x + ((size_t)(b * Lv + c * LCv)) * 256 + d2;
    float2 s = ((const float2*)g_pctx)[(size_t)bc * 256 + d2];
    __half2* xc = (__half2*)g_xcath;
    for (int i = 0; i < LCv; i += 2) {
        float2 a = xp[(size_t)i * 256];
        float2 e = xp[(size_t)(i + 1) * 256];
        int l0 = c * LCv + i;
        size_t row0 = (size_t)(b * Lv + l0) * 512;
        s.x += a.x; s.y += a.y;
        float inv0 = 1.f / (float)(l0 + 1);
        xc[row0 + d2] = __floats2half2_rn(a.x, a.y);
        xc[row0 + 256 + d2] = __floats2half2_rn(s.x * inv0, s.y * inv0);
        size_t row1 = row0 + 512;
        s.x += e.x; s.y += e.y;
        float inv1 = 1.f / (float)(l0 + 2);
        xc[row1 + d2] = __floats2half2_rn(e.x, e.y);
        xc[row1 + 256 + d2] = __floats2half2_rn(s.x * inv1, s.y * inv1);
    }
}

// ================= mem1 scan + fused pos_ret (2-channel half2, 2-token unroll) =================
__global__ void mem1_p1(const float* __restrict__ pos) {
    int bc = blockIdx.x; int b = bc >> NC_SH, c = bc & NC_MASK;
    int d2 = blockIdx.y * 128 + threadIdx.x;
    size_t base2 = ((size_t)(b * Lv + c * LCv)) * 256 + d2;
    const __half2* magp = (const __half2*)g_magh;
    const __half2* v1p  = (const __half2*)g_v1h;
    const float2* posp  = (const float2*)pos;
    float sc0 = 0.f, ss0 = 0.f, sm0 = 0.f, sc1 = 0.f, ss1 = 0.f, sm1 = 0.f;
    for (int i = 0; i < LCv; i += 2) {
        __half2 m0 = magp[base2 + (size_t)i * 256];
        __half2 w0 = v1p[base2 + (size_t)i * 256];
        __half2 m1 = magp[base2 + (size_t)(i + 1) * 256];
        __half2 w1 = v1p[base2 + (size_t)(i + 1) * 256];
        int lg = c * LCv + i;
        float2 p0 = posp[(size_t)lg * 256 + d2];
        float2 p1 = posp[(size_t)(lg + 1) * 256 + d2];
        float2 mf = __half22float2(m0), vf = __half22float2(w0);
        float sphi, cphi;
        sincosf(p0.x, &sphi, &cphi);
        float wgt = mf.x * vf.x;
        sc0 += wgt * cphi; ss0 += wgt * sphi; sm0 += mf.x;
        sincosf(p0.y, &sphi, &cphi);
        wgt = mf.y * vf.y;
        sc1 += wgt * cphi; ss1 += wgt * sphi; sm1 += mf.y;
        mf = __half22float2(m1); vf = __half22float2(w1);
        sincosf(p1.x, &sphi, &cphi);
        wgt = mf.x * vf.x;
        sc0 += wgt * cphi; ss0 += wgt * sphi; sm0 += mf.x;
        sincosf(p1.y, &sphi, &cphi);
        wgt = mf.y * vf.y;
        sc1 += wgt * cphi; ss1 += wgt * sphi; sm1 += mf.y;
    }
    size_t o2 = (size_t)bc * 256 + d2;
    ((float2*)g_pmc)[o2] = make_float2(sc0, sc1);
    ((float2*)g_pms)[o2] = make_float2(ss0, ss1);
    ((float2*)g_pmm)[o2] = make_float2(sm0, sm1);
}
__global__ void mem1_p2() {
    int idx = blockIdx.x * blockDim.x + threadIdx.x;
    if (idx >= Bv * Dv) return;
    int sel = blockIdx.y;
    float* arr = (sel == 0) ? g_pmc : ((sel == 1) ? g_pms : g_pmm);
    int b = idx / Dv, d = idx % Dv;
    float v[NCv];
#pragma unroll
    for (int c = 0; c < NCv; c++)
        v[c] = arr[((size_t)(b * NCv + c)) * Dv + d];
    float run = 0.f;
#pragma unroll
    for (int c = 0; c < NCv; c++) { float t = v[c]; v[c] = run; run += t; }
#pragma unroll
    for (int c = 0; c < NCv; c++)
        arr[((size_t)(b * NCv + c)) * Dv + d] = v[c];
}
__global__ void mem1_p3(const float* __restrict__ pos) {
    int bc = blockIdx.x; int b = bc >> NC_SH, c = bc & NC_MASK;
    int d2 = blockIdx.y * 128 + threadIdx.x;
    size_t base2 = ((size_t)(b * Lv + c * LCv)) * 256 + d2;
    size_t po2 = (size_t)bc * 256 + d2;
    const __half2* magp = (const __half2*)g_magh;
    const __half2* v1p  = (const __half2*)g_v1h;
    const __half2* qdp  = (const __half2*)g_qdh;
    const float2* posp  = (const float2*)pos;
    __half2* outp = (__half2*)g_posreth;
    float2 scv = ((const float2*)g_pmc)[po2];
    float2 ssv = ((const float2*)g_pms)[po2];
    float2 smv = ((const float2*)g_pmm)[po2];
    for (int i = 0; i < LCv; i += 2) {
        __half2 m0 = magp[base2 + (size_t)i * 256];
        __half2 w0 = v1p[base2 + (size_t)i * 256];
        __half2 q0 = qdp[base2 + (size_t)i * 256];
        __half2 m1 = magp[base2 + (size_t)(i + 1) * 256];
        __half2 w1 = v1p[base2 + (size_t)(i + 1) * 256];
        __half2 q1 = qdp[base2 + (size_t)(i + 1) * 256];
        int lg = c * LCv + i;
        float2 p0 = posp[(size_t)lg * 256 + d2];
        float2 p1 = posp[(size_t)(lg + 1) * 256 + d2];
#pragma unroll
        for (int u = 0; u < 2; u++) {
            float2 mf = __half22float2(u ? m1 : m0);
            float2 vf = __half22float2(u ? w1 : w0);
            float2 qf = __half22float2(u ? q1 : q0);
            float2 pp = u ? p1 : p0;
            float sphi, cphi, sq, cq;
            sincosf(pp.x, &sphi, &cphi);
            float wgt = mf.x * vf.x;
            scv.x += wgt * cphi; ssv.x += wgt * sphi; smv.x += mf.x;
            sincosf(pp.x + qf.x, &sq, &cq);
            float r0 = (scv.x * cq + ssv.x * sq) * rsqrtf(smv.x + 1e-8f) * INV_SQRT_D;
            sincosf(pp.y, &sphi, &cphi);
            wgt = mf.y * vf.y;
            scv.y += wgt * cphi; ssv.y += wgt * sphi; smv.y += mf.y;
            sincosf(pp.y + qf.y, &sq, &cq);
            float r1 = (scv.y * cq + ssv.y * sq) * rsqrtf(smv.y + 1e-8f) * INV_SQRT_D;
            outp[base2 + (size_t)(i + u) * 256] = __floats2half2_rn(r0, r1);
        }
    }
}

// ================= kv phasor scan: 8-token chunked, warp-per-v =================
__global__ void __launch_bounds__(256) kv_p1() {
    __shared__ float s_csp[8][128], s_ssp[8][128];
    __shared__ float s_gv[8][8], s_gate[8];
    int bc = blockIdx.x; int b = bc >> NC_SH, c = bc & NC_MASK;
    int tid = threadIdx.x, w = tid >> 5, l = tid & 31;
    int mbase = b * Lv + c * LCv;
    float aC[4] = {0, 0, 0, 0}, aS[4] = {0, 0, 0, 0};
    float gs = 0.f;
    for (int r0 = 0; r0 < LCv; r0 += 8) {
#pragma unroll
        for (int e = tid; e < 1024; e += 256) {
            int i = e >> 7, p = e & 127;
            size_t mm = (size_t)(mbase + r0 + i) * 128 + p;
            s_csp[i][p] = __half2float(g_csph[mm]);
            s_ssp[i][p] = __half2float(g_ssph[mm]);
        }
        if (tid < 64) s_gv[tid >> 3][tid & 7] = g_gvraw[(size_t)(mbase + r0 + (tid >> 3)) * 8 + (tid & 7)];
        if (tid < 8) s_gate[tid] = g_gate[mbase + r0 + tid];
        __syncthreads();
#pragma unroll
        for (int i = 0; i < 8; i++) {
            float gvv = s_gv[i][w] * s_gate[i];
            float4 cv = ((const float4*)s_csp[i])[l];
            float4 sv = ((const float4*)s_ssp[i])[l];
            aC[0] += cv.x * gvv; aC[1] += cv.y * gvv;
            aC[2] += cv.z * gvv; aC[3] += cv.w * gvv;
            aS[0] += sv.x * gvv; aS[1] += sv.y * gvv;
            aS[2] += sv.z * gvv; aS[3] += sv.w * gvv;
            gs += s_gate[i];
        }
        __syncthreads();
    }
#pragma unroll
    for (int j = 0; j < 4; j++) {
        size_t o = (size_t)bc * 1024 + (size_t)(4 * l + j) * 8 + w;
        g_pkc[o] = aC[j]; g_pks[o] = aS[j];
    }
    if (tid == 0) g_pg[bc] = gs;
}
__global__ void kv_p2() {
    int idx = blockIdx.x * blockDim.x + threadIdx.x;
    if (idx < Bv * Pv * Vv) {
        float* arr = blockIdx.y ? g_pks : g_pkc;
        int b = idx >> 10, pv = idx & 1023;
        float v[NCv];
#pragma unroll
        for (int c = 0; c < NCv; c++)
            v[c] = arr[((size_t)(b * NCv + c)) * 1024 + pv];
        float run = 0.f;
#pragma unroll
        for (int c = 0; c < NCv; c++) { float t = v[c]; v[c] = run; run += t; }
#pragma unroll
        for (int c = 0; c < NCv; c++)
            arr[((size_t)(b * NCv + c)) * 1024 + pv] = v[c];
    }
    if (blockIdx.x == 0 && blockIdx.y == 0 && idx < Bv) {
        float v[NCv];
#pragma unroll
        for (int c = 0; c < NCv; c++) v[c] = g_pg[(size_t)idx * NCv + c];
        float run = 0.f;
#pragma unroll
        for (int c = 0; c < NCv; c++) { float t = v[c]; v[c] = run; run += t; }
#pragma unroll
        for (int c = 0; c < NCv; c++) g_pg[(size_t)idx * NCv + c] = v[c];
    }
}
__global__ void __launch_bounds__(256) kv_p3(
    const float* __restrict__ w_kv, const float* __restrict__ b_kv)
{
    __shared__ float s_csp[8][128], s_ssp[8][128], s_cqp[8][128], s_sqp[8][128];
    __shared__ float s_gv[8][8], s_gate[8], s_kvr[8][8];
    __shared__ float s_wkv[8 * 512];
    __shared__ float s_bkv[512];
    int bc = blockIdx.x; int b = bc >> NC_SH, c = bc & NC_MASK;
    int tid = threadIdx.x, w = tid >> 5, l = tid & 31;
    int mbase = b * Lv + c * LCv;
    for (int i = tid; i < 8 * 512; i += 256) s_wkv[i] = w_kv[i];
    for (int i = tid; i < 512; i += 256) s_bkv[i] = b_kv[i];
    float aC[4], aS[4];
#pragma unroll
    for (int j = 0; j < 4; j++) {
        size_t o = (size_t)bc * 1024 + (size_t)(4 * l + j) * 8 + w;
        aC[j] = g_pkc[o]; aS[j] = g_pks[o];
    }
    float gsum = g_pg[bc];
    for (int r0 = 0; r0 < LCv; r0 += 8) {
#pragma unroll
        for (int e = tid; e < 1024; e += 256) {
            int i = e >> 7, p = e & 127;
            size_t mm = (size_t)(mbase + r0 + i) * 128 + p;
            s_csp[i][p] = __half2float(g_csph[mm]);
            s_ssp[i][p] = __half2float(g_ssph[mm]);
            s_cqp[i][p] = __half2float(g_cqph[mm]);
            s_sqp[i][p] = __half2float(g_sqph[mm]);
        }
        if (tid < 64) s_gv[tid >> 3][tid & 7] = g_gvraw[(size_t)(mbase + r0 + (tid >> 3)) * 8 + (tid & 7)];
        if (tid < 8) s_gate[tid] = g_gate[mbase + r0 + tid];
        __syncthreads();
#pragma unroll
        for (int i = 0; i < 8; i++) {
            float gvv = s_gv[i][w] * s_gate[i];
            float4 cv = ((const float4*)s_csp[i])[l];
            float4 sv = ((const float4*)s_ssp[i])[l];
            float4 cq = ((const float4*)s_cqp[i])[l];
            float4 sq = ((const float4*)s_sqp[i])[l];
            aC[0] += cv.x * gvv; aS[0] += sv.x * gvv;
            aC[1] += cv.y * gvv; aS[1] += sv.y * gvv;
            aC[2] += cv.z * gvv; aS[2] += sv.z * gvv;
            aC[3] += cv.w * gvv; aS[3] += sv.w * gvv;
            float pr = cq.x * aC[0] + sq.x * aS[0]
                     + cq.y * aC[1] + sq.y * aS[1]
                     + cq.z * aC[2] + sq.z * aS[2]
                     + cq.w * aC[3] + sq.w * aS[3];
#pragma unroll
            for (int o = 16; o; o >>= 1)
                pr += __shfl_xor_sync(0xffffffffu, pr, o);
            gsum += s_gate[i];
            if (l == 0)
                s_kvr[i][w] = pr * rsqrtf(fmaxf(gsum, 1.0f)) * INV_SQRT_P;
        }
        __syncthreads();
#pragma unroll
        for (int k = 0; k < 16; k++) {
            int idx = tid + k * 256;
            int tok = idx >> 9, n = idx & 511;
            float o = s_bkv[n];
#pragma unroll
            for (int v = 0; v < 8; v++)
                o += s_kvr[tok][v] * s_wkv[v * 512 + n];
            g_ccath[(size_t)(mbase + r0 + tok) * 1024 + 512 + n] = __float2half_rn(o);
        }
        __syncthreads();
    }
}

// ================= LayerNorm (half in/out) =================
__global__ void __launch_bounds__(256) ln_kernel(
    const float* __restrict__ lng, const float* __restrict__ lnb)
{
    int m = blockIdx.x, tid = threadIdx.x;
    const __half2* row = (const __half2*)(g_ccath + (size_t)m * 1024);
    __half2 h0 = row[tid * 2], h1 = row[tid * 2 + 1];
    float2 f0 = __half22float2(h0), f1 = __half22float2(h1);
    float s = f0.x + f0.y + f1.x + f1.y;
    float q = f0.x * f0.x + f0.y * f0.y + f1.x * f1.x + f1.y * f1.y;
#pragma unroll
    for (int o = 16; o; o >>= 1) {
        s += __shfl_xor_sync(0xffffffffu, s, o);
        q += __shfl_xor_sync(0xffffffffu, q, o);
    }
    __shared__ float ss[8], sq[8];
    __shared__ float smu, srs;
    if ((tid & 31) == 0) { ss[tid >> 5] = s; sq[tid >> 5] = q; }
    __syncthreads();
    if (tid == 0) {
        float S = 0.f, Q = 0.f;
#pragma unroll
        for (int w = 0; w < 8; w++) { S += ss[w]; Q += sq[w]; }
        float mu = S * (1.f / 1024.f);
        float var = Q * (1.f / 1024.f) - mu * mu;
        smu = mu; srs = rsqrtf(var + 1e-5f);
    }
    __syncthreads();
    float mu = smu, rs = srs;
    float4 g4 = ((const float4*)lng)[tid];
    float4 b4 = ((const float4*)lnb)[tid];
    __half2* oh = (__half2*)(g_lnh + (size_t)m * 1024);
    oh[tid * 2]     = __floats2half2_rn((f0.x - mu) * rs * g4.x + b4.x,
                                        (f0.y - mu) * rs * g4.y + b4.y);
    oh[tid * 2 + 1] = __floats2half2_rn((f1.x - mu) * rs * g4.z + b4.z,
                                        (f1.y - mu) * rs * g4.w + b4.w);
}

// ================= launch =================
extern "C" void kernel_launch(void* const* d_in, const int* in_sizes, int n_in,
                              void* d_out, int out_size)
{
    const float* x    = (const float*)d_in[0];
    const float* pos  = (const float*)d_in[1];
    const float* ms   = (const float*)d_in[2];
    const float* w_v  = (const float*)d_in[3];
    const float* b_v  = (const float*)d_in[4];
    const float* w_o  = (const float*)d_in[5];
    const float* b_o  = (const float*)d_in[6];
    const float* w_m  = (const float*)d_in[7];
    const float* b_m  = (const float*)d_in[8];
    const float* w_q  = (const float*)d_in[9];
    const float* b_q  = (const float*)d_in[10];
    const float* w_ke = (const float*)d_in[11];
    const float* b_ke = (const float*)d_in[12];
    const float* w_ve = (const float*)d_in[13];
    const float* b_ve = (const float*)d_in[14];
    const float* w_s1 = (const float*)d_in[15];
    const float* b_s1 = (const float*)d_in[16];
    const float* w_s2 = (const float*)d_in[17];
    const float* b_s2 = (const float*)d_in[18];
    const float* w_g  = (const float*)d_in[19];
    const float* b_g  = (const float*)d_in[20];
    const float* w_kv = (const float*)d_in[21];
    const float* b_kv = (const float*)d_in[22];
    const float* lng  = (const float*)d_in[23];
    const float* lnb  = (const float*)d_in[24];
    const float* w_t1 = (const float*)d_in[25];
    const float* b_t1 = (const float*)d_in[26];
    const float* w_t2 = (const float*)d_in[27];
    const float* b_t2 = (const float*)d_in[28];
    float* out = (float*)d_out;

    float *p_bcat;
    __half *p_wth, *p_xcath, *p_v1h, *p_magh, *p_qdh, *p_cqph, *p_sqph,
           *p_csph, *p_ssph, *p_s1gh, *p_posreth, *p_ccath, *p_lnh, *p_h1h;
    cudaGetSymbolAddress((void**)&p_bcat, g_bcat);
    cudaGetSymbolAddress((void**)&p_wth, g_wth);
    cudaGetSymbolAddress((void**)&p_xcath, g_xcath);
    cudaGetSymbolAddress((void**)&p_v1h, g_v1h);
    cudaGetSymbolAddress((void**)&p_magh, g_magh);
    cudaGetSymbolAddress((void**)&p_qdh, g_qdh);
    cudaGetSymbolAddress((void**)&p_cqph, g_cqph);
    cudaGetSymbolAddress((void**)&p_sqph, g_sqph);
    cudaGetSymbolAddress((void**)&p_csph, g_csph);
    cudaGetSymbolAddress((void**)&p_ssph, g_ssph);
    cudaGetSymbolAddress((void**)&p_s1gh, g_s1gh);
    cudaGetSymbolAddress((void**)&p_posreth, g_posreth);
    cudaGetSymbolAddress((void**)&p_ccath, g_ccath);
    cudaGetSymbolAddress((void**)&p_lnh, g_lnh);
    cudaGetSymbolAddress((void**)&p_h1h, g_h1h);

    __half* wt_proj = p_wth + WT_PROJ;
    __half* wt_o    = p_wth + WT_O;
    __half* wt_s1   = p_wth + WT_S1;
    __half* wt_s2   = p_wth + WT_S2;
    __half* wt_t1   = p_wth + WT_T1;
    __half* wt_t2   = p_wth + WT_T2;

    const int SMEM = 2 * STAGE_H * 2;  // 40960 B
    cudaFuncSetAttribute(mma_gemm, cudaFuncAttributeMaxDynamicSharedMemorySize, SMEM);

    TTable tt;
    tt.src[0] = w_v;  tt.dst[0] = wt_proj;              tt.K[0] = 512;  tt.N[0] = 512;
    tt.src[1] = w_m;  tt.dst[1] = wt_proj + 512 * 512;  tt.K[1] = 512;  tt.N[1] = 512;
    tt.src[2] = w_q;  tt.dst[2] = wt_proj + 1024 * 512; tt.K[2] = 512;  tt.N[2] = 512;
    tt.src[3] = w_ke; tt.dst[3] = wt_proj + 1536 * 512; tt.K[3] = 512;  tt.N[3] = 128;
    tt.src[4] = w_o;  tt.dst[4] = wt_o;                 tt.K[4] = 512;  tt.N[4] = 512;
    tt.src[5] = w_s1; tt.dst[5] = wt_s1;                tt.K[5] = 1024; tt.N[5] = 512;
    tt.src[6] = w_s2; tt.dst[6] = wt_s2;                tt.K[6] = 512;  tt.N[6] = 128;
    tt.src[7] = w_t1; tt.dst[7] = wt_t1;                tt.K[7] = 1024; tt.N[7] = 1024;
    tt.src[8] = w_t2; tt.dst[8] = wt_t2;                tt.K[8] = 1024; tt.N[8] = 512;
    int acc = 0;
    for (int i = 0; i < 9; i++) {
        tt.t0[i] = acc;
        acc += (tt.K[i] >> 5) * (tt.N[i] >> 5);
    }

    // ---- fork/join streams (created per call; never destroyed: kernel_launch
    //      is invoked only a handful of times and streams/events are host objects) ----
    cudaStream_t sB;
    cudaStreamCreateWithFlags(&sB, cudaStreamNonBlocking);
    cudaEvent_t evStart, evSetup, evCtx, evProj, evKv;
    cudaEventCreateWithFlags(&evStart, cudaEventDisableTiming);
    cudaEventCreateWithFlags(&evSetup, cudaEventDisableTiming);
    cudaEventCreateWithFlags(&evCtx, cudaEventDisableTiming);
    cudaEventCreateWithFlags(&evProj, cudaEventDisableTiming);
    cudaEventCreateWithFlags(&evKv, cudaEventDisableTiming);

    dim3 tb(256);
    dim3 gScan2(Bv * NCv, 2);

    // fork B off the capture origin
    cudaEventRecord(evStart, 0);
    cudaStreamWaitEvent(sB, evStart, 0);

    // ---- stream B: weight setup ----
    transpose_all<<<acc, 256, 0, sB>>>(tt);
    pack_veg<<<18, 256, 0, sB>>>(w_ve, w_g);
    bias_concat<<<7, 256, 0, sB>>>(b_v, b_m, b_q, b_ke, b_ve, b_g);
    cudaEventRecord(evSetup, sB);

    // ---- stream 0: ctx chain ----
    ctx_p1<<<gScan2, 128>>>(x);
    ctx_p2<<<(Bv * Dv + 255) / 256, 256>>>();
    ctx_p3<<<gScan2, 128>>>(x);
    cudaEventRecord(evCtx, 0);

    // ---- stream 0: proj (needs setup + xcat) ----
    cudaStreamWaitEvent(0, evSetup, 0);
    mma_gemm<<<dim3(14, 128), tb, SMEM>>>(p_xcath, wt_proj, p_bcat,
        (float*)p_v1h, (float*)p_magh, (float*)p_qdh,
        (float*)p_cqph, (float*)p_sqph, 512, 1024, 512, 6, 0, ms);
    cudaEventRecord(evProj, 0);

    // ---- stream B: s1 -> s2 (needs xcat + setup; setup is B-ordered) ----
    cudaStreamWaitEvent(sB, evCtx, 0);
    mma_gemm<<<dim3(4, 128), tb, SMEM, sB>>>(p_xcath, wt_s1, b_s1,
        (float*)p_s1gh, nullptr, nullptr, nullptr, nullptr, 1024, 1024, 512, 2, 1, nullptr);
    mma_gemm<<<dim3(1, 128), tb, SMEM, sB>>>(p_s1gh, wt_s2, b_s2,
        (float*)p_csph, (float*)p_ssph, nullptr, nullptr, nullptr, 512, 512, 128, 5, 0, nullptr);

    // ---- stream B: kv chain (needs proj outputs gv/gate/cqp/sqp) ----
    cudaStreamWaitEvent(sB, evProj, 0);
    kv_p1<<<Bv * NCv, 256, 0, sB>>>();
    kv_p2<<<dim3((Bv * Pv * Vv + 255) / 256, 2), 256, 0, sB>>>();
    kv_p3<<<Bv * NCv, 256, 0, sB>>>(w_kv, b_kv);
    cudaEventRecord(evKv, sB);

    // ---- stream 0: mem1 chain + pos_out (needs proj outputs; 0-ordered) ----
    mem1_p1<<<gScan2, 128>>>(pos);
    mem1_p2<<<dim3((Bv * Dv + 255) / 256, 3), 256>>>();
    mem1_p3<<<gScan2, 128>>>(pos);
    mma_gemm<<<dim3(4, 128), tb, SMEM>>>(p_posreth, wt_o, b_o,
        (float*)p_ccath, nullptr, nullptr, nullptr, nullptr, 512, 512, 1024, 0, 1, nullptr);

    // ---- join: LN needs both ccat halves ----
    cudaStreamWaitEvent(0, evKv, 0);
    ln_kernel<<<Mv, 256>>>(lng, lnb);
    mma_gemm<<<dim3(8, 128), tb, SMEM>>>(p_lnh, wt_t1, b_t1,
        (float*)p_h1h, nullptr, nullptr, nullptr, nullptr, 1024, 1024, 1024, 2, 1, nullptr);
    mma_gemm<<<dim3(4, 128), tb, SMEM>>>(p_h1h, wt_t2, b_t2,
        out, nullptr, nullptr, nullptr, nullptr, 1024, 1024, 512, 4, 0, x);
}